// round 5
// baseline (speedup 1.0000x reference)
#include <cuda_runtime.h>
#include <cuda_bf16.h>
#include <math.h>
#include <stdint.h>

#define BB 8
#define LL 2048
#define CC 256
#define HH 4
#define DDIM 64
#define RR (BB*LL)          // 16384
#define C2 (2*CC)           // 512

typedef unsigned long long u64;
typedef unsigned int u32;
typedef __nv_bfloat16 bf16;

// ---- packed f32x2 helpers (flash) ----
__device__ __forceinline__ u64 pk2(float x, float y) {
    u64 r; asm("mov.b64 %0,{%1,%2};" : "=l"(r) : "f"(x), "f"(y)); return r;
}
__device__ __forceinline__ u64 pk1(float x) { return pk2(x, x); }
__device__ __forceinline__ void upk2(u64 v, float& x, float& y) {
    asm("mov.b64 {%0,%1},%2;" : "=f"(x), "=f"(y) : "l"(v));
}
__device__ __forceinline__ u64 f2fma(u64 a, u64 b, u64 c) {
    u64 d; asm("fma.rn.f32x2 %0,%1,%2,%3;" : "=l"(d) : "l"(a), "l"(b), "l"(c)); return d;
}
__device__ __forceinline__ u64 f2mul(u64 a, u64 b) {
    u64 d; asm("mul.rn.f32x2 %0,%1,%2;" : "=l"(d) : "l"(a), "l"(b)); return d;
}
union F4U { float4 f4; u64 u[2]; };

__device__ __forceinline__ void split1(float x, bf16& h_, bf16& l_) {
    h_ = __float2bfloat16(x);
    l_ = __float2bfloat16(x - __bfloat162float(h_));
}

__device__ __forceinline__ u32 smem_u32(const void* p) {
    u32 a;
    asm("{ .reg .u64 t; cvta.to.shared.u64 t, %1; cvt.u32.u64 %0, t; }"
        : "=r"(a) : "l"(p));
    return a;
}

__device__ __forceinline__ void ldsm4(u32 addr, u32& r0, u32& r1, u32& r2, u32& r3) {
    asm volatile("ldmatrix.sync.aligned.m8n8.x4.shared.b16 {%0,%1,%2,%3}, [%4];"
                 : "=r"(r0), "=r"(r1), "=r"(r2), "=r"(r3) : "r"(addr));
}

__device__ __forceinline__ void mma_bf16(float* c, const u32* a, const u32* b) {
    asm volatile(
        "mma.sync.aligned.m16n8k16.row.col.f32.bf16.bf16.f32 "
        "{%0,%1,%2,%3},{%4,%5,%6,%7},{%8,%9},{%0,%1,%2,%3};"
        : "+f"(c[0]), "+f"(c[1]), "+f"(c[2]), "+f"(c[3])
        : "r"(a[0]), "r"(a[1]), "r"(a[2]), "r"(a[3]), "r"(b[0]), "r"(b[1]));
}

// ===================== scratch =====================
__device__ float g_qk0[BB*HH*LL*DDIM];
__device__ float g_qk1[BB*HH*LL*DDIM];
__device__ float g_v0 [BB*HH*LL*DDIM];
__device__ float g_v1 [BB*HH*LL*DDIM];
__device__ float g_h0 [RR*C2];
__device__ float g_h1 [RR*C2];

__device__ bf16 g_x0h[RR*CC], g_x0l[RR*CC], g_x1h[RR*CC], g_x1l[RR*CC];
__device__ bf16 g_m0h[RR*CC], g_m0l[RR*CC], g_m1h[RR*CC], g_m1l[RR*CC];
__device__ bf16 g_p0h[RR*CC], g_p0l[RR*CC], g_p1h[RR*CC], g_p1l[RR*CC];
__device__ bf16 g_h0h[RR*C2], g_h0l[RR*C2], g_h1h[RR*C2], g_h1l[RR*C2];

__device__ bf16 g_Wqkh[CC*CC], g_Wqkl[CC*CC];
__device__ bf16 g_Wvh [CC*CC], g_Wvl [CC*CC];
__device__ bf16 g_Woth[CC*CC], g_Wotl[CC*CC];
__device__ bf16 g_W1h [C2*C2], g_W1l [C2*C2];
__device__ bf16 g_W2h [CC*C2], g_W2l [CC*C2];   // [N=256][K=512]

// ===================== split f32 -> bf16 hi/lo =====================
__global__ __launch_bounds__(256) void split_kernel(
    const float* __restrict__ x, bf16* __restrict__ hi, bf16* __restrict__ lo, int n)
{
    int i = (blockIdx.x * 256 + threadIdx.x) * 4;
    if (i >= n) return;
    float4 v = *(const float4*)(x + i);
    bf16 h0, l0, h1, l1, h2, l2, h3, l3;
    split1(v.x, h0, l0); split1(v.y, h1, l1);
    split1(v.z, h2, l2); split1(v.w, h3, l3);
    __nv_bfloat162 ph0, ph1, pl0, pl1;
    ph0.x = h0; ph0.y = h1; ph1.x = h2; ph1.y = h3;
    pl0.x = l0; pl0.y = l1; pl1.x = l2; pl1.y = l3;
    uint2 uh, ul;
    uh.x = *(u32*)&ph0; uh.y = *(u32*)&ph1;
    ul.x = *(u32*)&pl0; ul.y = *(u32*)&pl1;
    *(uint2*)(hi + i) = uh;
    *(uint2*)(lo + i) = ul;
}

// ===================== transpose W [K,N] -> split [N,K] =====================
__global__ __launch_bounds__(256) void wsplit_kernel(
    const float* __restrict__ W, bf16* __restrict__ hi, bf16* __restrict__ lo,
    int K, int N)
{
    __shared__ float t[32][33];
    int nb = blockIdx.x * 32, kb = blockIdx.y * 32;
    int tx = threadIdx.x, ty0 = threadIdx.y;  // block (32,8)
    #pragma unroll
    for (int r = 0; r < 4; r++) {
        int ty = ty0 + r * 8;
        t[ty][tx] = W[(size_t)(kb + ty) * N + nb + tx];
    }
    __syncthreads();
    #pragma unroll
    for (int r = 0; r < 4; r++) {
        int ty = ty0 + r * 8;
        float v = t[tx][ty];  // = W[kb+tx][nb+ty]
        bf16 h_, l_;
        split1(v, h_, l_);
        size_t o = (size_t)(nb + ty) * K + kb + tx;
        hi[o] = h_; lo[o] = l_;
    }
}

// ===================== mma.sync split-bf16 GEMM =====================
// out[M,N] = (concat(A0,A1)[M,K] @ W[K,N] + bias)*scale (+res)
// A,W as bf16 hi/lo; W transposed [N,K]. CTA 128x128, K chunk 64.
// 8 warps: warp tile 64x32 (grid 2m x 4n).
// mode: 0 = f32 out, 1 = f32 head-layout, 2 = split bf16 out
// smem: Ah 16K | Al 16K | Bh 16K | Bl 16K  (rows of 64 bf16 = 128B, XOR-swizzled)
#define MG_SMEM (64*1024 + 128)

__global__ __launch_bounds__(256, 2) void mma_gemm(
    const bf16* __restrict__ a0h, const bf16* __restrict__ a0l, int K0,
    const bf16* __restrict__ a1h, const bf16* __restrict__ a1l, int K1,
    const bf16* __restrict__ bh, const bf16* __restrict__ bl,
    const float* __restrict__ bias,
    const float* __restrict__ res,
    float* __restrict__ outf,
    bf16* __restrict__ outh, bf16* __restrict__ outl,
    int N, float scale, int mode)
{
    extern __shared__ char dsm[];
    u32 sb0 = smem_u32(dsm);
    u32 sb  = (sb0 + 127) & ~127u;
    char* smp = dsm + (sb - sb0);

    const int tid  = threadIdx.x;
    const int wid  = tid >> 5;
    const int lane = tid & 31;

    const int m0 = blockIdx.y * 128;
    const int n0 = blockIdx.x * 128;
    const int KB = K0 + K1;
    const int nc0 = K0 >> 6;
    const int nc  = KB >> 6;

    const int wm = (wid >> 2) * 64;   // 0 / 64
    const int wn = (wid & 3) * 32;    // 0..96

    const u32 sAh = sb;
    const u32 sAl = sb + 16384;
    const u32 sBh = sb + 32768;
    const u32 sBl = sb + 49152;

    float acc[4][4][4];
    #pragma unroll
    for (int i = 0; i < 4; i++)
        #pragma unroll
        for (int j = 0; j < 4; j++)
            #pragma unroll
            for (int t = 0; t < 4; t++) acc[i][j][t] = 0.f;

    // precompute load indices
    const int ld_row = tid >> 3;      // 0..31 (x4 reps -> 128 rows)
    const int ld_ch  = tid & 7;

    for (int c = 0; c < nc; c++) {
        __syncthreads();
        const bf16 *Ah, *Al;
        int astr, koff;
        if (c < nc0) { Ah = a0h; Al = a0l; astr = K0; koff = c << 6; }
        else         { Ah = a1h; Al = a1l; astr = K1; koff = (c - nc0) << 6; }
        const int koffB = c << 6;

        #pragma unroll
        for (int i = 0; i < 4; i++) {
            int row = ld_row + i * 32;
            u32 off = (u32)(row * 128 + ((ld_ch ^ (row & 7)) << 4));
            *(uint4*)(smp + off) =
                *(const uint4*)(Ah + (size_t)(m0 + row) * astr + koff + ld_ch * 8);
            *(uint4*)(smp + 16384 + off) =
                *(const uint4*)(Al + (size_t)(m0 + row) * astr + koff + ld_ch * 8);
            *(uint4*)(smp + 32768 + off) =
                *(const uint4*)(bh + (size_t)(n0 + row) * KB + koffB + ld_ch * 8);
            *(uint4*)(smp + 49152 + off) =
                *(const uint4*)(bl + (size_t)(n0 + row) * KB + koffB + ld_ch * 8);
        }
        __syncthreads();

        #pragma unroll
        for (int ks = 0; ks < 4; ks++) {
            const int cidx = ks * 2 + (lane >> 4);

            // B fragments (hi and lo): 4 n8-frags each
            u32 bfh[4][2], bfl[4][2];
            #pragma unroll
            for (int g = 0; g < 2; g++) {
                int rb = wn + g * 16 + (lane & 15);
                u32 off = (u32)(rb * 128 + ((cidx ^ (rb & 7)) << 4));
                u32 r0, r1, r2, r3;
                ldsm4(sBh + off, r0, r1, r2, r3);
                bfh[2*g][0] = r0; bfh[2*g][1] = r2;
                bfh[2*g+1][0] = r1; bfh[2*g+1][1] = r3;
                ldsm4(sBl + off, r0, r1, r2, r3);
                bfl[2*g][0] = r0; bfl[2*g][1] = r2;
                bfl[2*g+1][0] = r1; bfl[2*g+1][1] = r3;
            }

            // A-hi fragments
            u32 af[4][4];
            #pragma unroll
            for (int mi = 0; mi < 4; mi++) {
                int ra = wm + mi * 16 + (lane & 15);
                u32 off = (u32)(ra * 128 + ((cidx ^ (ra & 7)) << 4));
                ldsm4(sAh + off, af[mi][0], af[mi][1], af[mi][2], af[mi][3]);
            }
            #pragma unroll
            for (int mi = 0; mi < 4; mi++)
                #pragma unroll
                for (int nj = 0; nj < 4; nj++)
                    mma_bf16(acc[mi][nj], af[mi], bfh[nj]);
            #pragma unroll
            for (int mi = 0; mi < 4; mi++)
                #pragma unroll
                for (int nj = 0; nj < 4; nj++)
                    mma_bf16(acc[mi][nj], af[mi], bfl[nj]);

            // A-lo fragments (reuse regs)
            #pragma unroll
            for (int mi = 0; mi < 4; mi++) {
                int ra = wm + mi * 16 + (lane & 15);
                u32 off = (u32)(ra * 128 + ((cidx ^ (ra & 7)) << 4));
                ldsm4(sAl + off, af[mi][0], af[mi][1], af[mi][2], af[mi][3]);
            }
            #pragma unroll
            for (int mi = 0; mi < 4; mi++)
                #pragma unroll
                for (int nj = 0; nj < 4; nj++)
                    mma_bf16(acc[mi][nj], af[mi], bfh[nj]);
        }
    }

    // ---------------- epilogue ----------------
    const int lr = lane >> 2;
    const int lc = (lane & 3) * 2;
    #pragma unroll
    for (int mi = 0; mi < 4; mi++) {
        #pragma unroll
        for (int half = 0; half < 2; half++) {
            int r = m0 + wm + mi * 16 + lr + half * 8;
            #pragma unroll
            for (int nj = 0; nj < 4; nj++) {
                int col = n0 + wn + nj * 8 + lc;
                float2 bv = *(const float2*)(bias + col);
                float v0 = (acc[mi][nj][half * 2]     + bv.x) * scale;
                float v1 = (acc[mi][nj][half * 2 + 1] + bv.y) * scale;
                if (mode == 1) {
                    int b_ = r >> 11, l = r & 2047;
                    int h  = col >> 6, d = col & 63;
                    size_t o = (((size_t)(b_ * HH + h)) * LL + l) * DDIM + d;
                    *(float2*)(outf + o) = make_float2(v0, v1);
                } else if (mode == 0) {
                    size_t o = (size_t)r * N + col;
                    if (res) {
                        float2 rv = *(const float2*)(res + o);
                        v0 += rv.x; v1 += rv.y;
                    }
                    *(float2*)(outf + o) = make_float2(v0, v1);
                } else {
                    size_t o = (size_t)r * N + col;
                    bf16 ha, la, hb, lb_;
                    split1(v0, ha, la);
                    split1(v1, hb, lb_);
                    __nv_bfloat162 th, tl;
                    th.x = ha; th.y = hb; tl.x = la; tl.y = lb_;
                    *(u32*)(outh + o) = *(u32*)&th;
                    *(u32*)(outl + o) = *(u32*)&tl;
                }
            }
        }
    }
}

// ===================== flash attention (f32x2, split-bf16 output) =====================
#define QT_STR 132
#define KT_STR 68
#define VS_STR 68
#define PT_STR 132
#define OFF_KT (64*QT_STR)
#define OFF_VS (OFF_KT + 64*KT_STR)
#define OFF_PT (OFF_VS + 64*VS_STR)
#define FLASH_SMEM_FLOATS (OFF_PT + 64*PT_STR)

__global__ __launch_bounds__(256, 2) void flash_kernel(
    const float* __restrict__ qk0, const float* __restrict__ qk1,
    const float* __restrict__ v0f, const float* __restrict__ v1f,
    bf16* __restrict__ m0h, bf16* __restrict__ m0l,
    bf16* __restrict__ m1h, bf16* __restrict__ m1l)
{
    extern __shared__ float sm[];
    float* Qt = sm;
    float* Kt = sm + OFF_KT;
    float* Vs = sm + OFF_VS;
    float* Pt = sm + OFF_PT;

    const int dir = blockIdx.z;
    const float* qp = dir ? qk1 : qk0;
    const float* kp = dir ? qk0 : qk1;
    const float* vp = dir ? v0f : v1f;
    bf16* oh = dir ? m1h : m0h;
    bf16* ol = dir ? m1l : m0l;

    const int bh = blockIdx.y;
    const size_t base = (size_t)bh * LL * DDIM;
    const int q0 = blockIdx.x * 128;
    const int tid = threadIdx.x;
    const int tr = tid >> 4;
    const int tc = tid & 15;

    #pragma unroll
    for (int rep = 0; rep < 8; rep++) {
        int idx = rep * 256 + tid;
        int qrow = idx >> 4;
        int d4   = (idx & 15) * 4;
        float4 qv = *(const float4*)&qp[base + (size_t)(q0 + qrow) * DDIM + d4];
        Qt[(d4 + 0) * QT_STR + qrow] = qv.x;
        Qt[(d4 + 1) * QT_STR + qrow] = qv.y;
        Qt[(d4 + 2) * QT_STR + qrow] = qv.z;
        Qt[(d4 + 3) * QT_STR + qrow] = qv.w;
    }

    float m_i[8], l_i[8];
    u64 o[8][2];
    #pragma unroll
    for (int i = 0; i < 8; i++) {
        m_i[i] = -1e30f; l_i[i] = 0.f;
        o[i][0] = 0ULL; o[i][1] = 0ULL;
    }

    for (int k0 = 0; k0 < LL; k0 += 64) {
        __syncthreads();
        #pragma unroll
        for (int rep = 0; rep < 4; rep++) {
            int idx = rep * 256 + tid;
            int krow = idx >> 4;
            int d4   = (idx & 15) * 4;
            float4 kv = *(const float4*)&kp[base + (size_t)(k0 + krow) * DDIM + d4];
            Kt[(d4 + 0) * KT_STR + krow] = kv.x;
            Kt[(d4 + 1) * KT_STR + krow] = kv.y;
            Kt[(d4 + 2) * KT_STR + krow] = kv.z;
            Kt[(d4 + 3) * KT_STR + krow] = kv.w;
            float4 vv = *(const float4*)&vp[base + (size_t)(k0 + krow) * DDIM + d4];
            *(float4*)&Vs[krow * VS_STR + d4] = vv;
        }
        __syncthreads();

        u64 s[8][2];
        #pragma unroll
        for (int i = 0; i < 8; i++) { s[i][0] = 0ULL; s[i][1] = 0ULL; }

        const float* qpt = Qt + tr * 8;
        const float* kpt = Kt + tc * 4;
        #pragma unroll 16
        for (int d = 0; d < 64; d++) {
            float af[8];
            *(float4*)&af[0] = *(float4*)&qpt[d * QT_STR];
            *(float4*)&af[4] = *(float4*)&qpt[d * QT_STR + 4];
            F4U bb; bb.f4 = *(float4*)&kpt[d * KT_STR];
            #pragma unroll
            for (int i = 0; i < 8; i++) {
                u64 ap = pk1(af[i]);
                s[i][0] = f2fma(ap, bb.u[0], s[i][0]);
                s[i][1] = f2fma(ap, bb.u[1], s[i][1]);
            }
        }

        float sv[8][4];
        #pragma unroll
        for (int i = 0; i < 8; i++) {
            upk2(s[i][0], sv[i][0], sv[i][1]);
            upk2(s[i][1], sv[i][2], sv[i][3]);
        }
        #pragma unroll
        for (int i = 0; i < 8; i++) {
            float mt = fmaxf(fmaxf(sv[i][0], sv[i][1]), fmaxf(sv[i][2], sv[i][3]));
            mt = fmaxf(mt, __shfl_xor_sync(0xffffffffu, mt, 1));
            mt = fmaxf(mt, __shfl_xor_sync(0xffffffffu, mt, 2));
            mt = fmaxf(mt, __shfl_xor_sync(0xffffffffu, mt, 4));
            mt = fmaxf(mt, __shfl_xor_sync(0xffffffffu, mt, 8));
            float mn = fmaxf(m_i[i], mt);
            float al = __expf(m_i[i] - mn);
            float ps = 0.f;
            #pragma unroll
            for (int j = 0; j < 4; j++) {
                sv[i][j] = __expf(sv[i][j] - mn);
                ps += sv[i][j];
            }
            ps += __shfl_xor_sync(0xffffffffu, ps, 1);
            ps += __shfl_xor_sync(0xffffffffu, ps, 2);
            ps += __shfl_xor_sync(0xffffffffu, ps, 4);
            ps += __shfl_xor_sync(0xffffffffu, ps, 8);
            l_i[i] = l_i[i] * al + ps;
            m_i[i] = mn;
            u64 av = pk1(al);
            o[i][0] = f2mul(o[i][0], av);
            o[i][1] = f2mul(o[i][1], av);
        }

        #pragma unroll
        for (int jj = 0; jj < 4; jj++) {
            float4 lo, hi;
            lo.x = sv[0][jj]; lo.y = sv[1][jj]; lo.z = sv[2][jj]; lo.w = sv[3][jj];
            hi.x = sv[4][jj]; hi.y = sv[5][jj]; hi.z = sv[6][jj]; hi.w = sv[7][jj];
            *(float4*)&Pt[(tc * 4 + jj) * PT_STR + tr * 8]     = lo;
            *(float4*)&Pt[(tc * 4 + jj) * PT_STR + tr * 8 + 4] = hi;
        }
        __syncthreads();

        const float* ppt = Pt + tr * 8;
        const float* vpt = Vs + tc * 4;
        #pragma unroll 16
        for (int j = 0; j < 64; j++) {
            float af[8];
            *(float4*)&af[0] = *(float4*)&ppt[j * PT_STR];
            *(float4*)&af[4] = *(float4*)&ppt[j * PT_STR + 4];
            F4U bb; bb.f4 = *(float4*)&vpt[j * VS_STR];
            #pragma unroll
            for (int i = 0; i < 8; i++) {
                u64 ap = pk1(af[i]);
                o[i][0] = f2fma(ap, bb.u[0], o[i][0]);
                o[i][1] = f2fma(ap, bb.u[1], o[i][1]);
            }
        }
    }

    const int b_ = bh >> 2;
    const int h  = bh & 3;
    #pragma unroll
    for (int i = 0; i < 8; i++) {
        float inv = 1.f / l_i[i];
        float ov[4];
        upk2(o[i][0], ov[0], ov[1]);
        upk2(o[i][1], ov[2], ov[3]);
        #pragma unroll
        for (int t = 0; t < 4; t++) ov[t] *= inv;
        size_t orow = ((size_t)(b_ * LL + q0 + tr * 8 + i)) * CC + h * DDIM + tc * 4;
        bf16 ha[4], la[4];
        #pragma unroll
        for (int t = 0; t < 4; t++) split1(ov[t], ha[t], la[t]);
        uint2 uh, ul;
        __nv_bfloat162 t0, t1;
        t0.x = ha[0]; t0.y = ha[1]; t1.x = ha[2]; t1.y = ha[3];
        uh.x = *(u32*)&t0; uh.y = *(u32*)&t1;
        t0.x = la[0]; t0.y = la[1]; t1.x = la[2]; t1.y = la[3];
        ul.x = *(u32*)&t0; ul.y = *(u32*)&t1;
        *(uint2*)(oh + orow) = uh;
        *(uint2*)(ol + orow) = ul;
    }
}

// ===================== LayerNorm + exact GELU -> split bf16 =====================
__global__ __launch_bounds__(256) void ln_gelu_kernel(
    const float* __restrict__ h0, const float* __restrict__ h1,
    bf16* __restrict__ h0h, bf16* __restrict__ h0l,
    bf16* __restrict__ h1h, bf16* __restrict__ h1l,
    const float* __restrict__ g, const float* __restrict__ bta)
{
    const float* hp = blockIdx.y ? h1 : h0;
    bf16* oh = blockIdx.y ? h1h : h0h;
    bf16* olo = blockIdx.y ? h1l : h0l;
    const size_t rowoff = (size_t)blockIdx.x * C2;
    const int tid = threadIdx.x;
    const int lane = tid & 31, wid = tid >> 5;

    float2 v = *(const float2*)&hp[rowoff + tid * 2];
    float s  = v.x + v.y;
    float sq = v.x * v.x + v.y * v.y;
    #pragma unroll
    for (int off = 16; off; off >>= 1) {
        s  += __shfl_xor_sync(0xffffffffu, s,  off);
        sq += __shfl_xor_sync(0xffffffffu, sq, off);
    }
    __shared__ float rs[8], rq[8];
    if (lane == 0) { rs[wid] = s; rq[wid] = sq; }
    __syncthreads();
    if (wid == 0) {
        s  = (lane < 8) ? rs[lane] : 0.f;
        sq = (lane < 8) ? rq[lane] : 0.f;
        #pragma unroll
        for (int off = 4; off; off >>= 1) {
            s  += __shfl_xor_sync(0xffffffffu, s,  off);
            sq += __shfl_xor_sync(0xffffffffu, sq, off);
        }
        if (lane == 0) { rs[0] = s; rq[0] = sq; }
    }
    __syncthreads();
    float mean = rs[0] * (1.f / 512.f);
    float var  = rq[0] * (1.f / 512.f) - mean * mean;
    float rstd = rsqrtf(var + 1e-5f);

    int c0 = tid * 2;
    float x0n = (v.x - mean) * rstd * g[c0]     + bta[c0];
    float x1n = (v.y - mean) * rstd * g[c0 + 1] + bta[c0 + 1];
    x0n = 0.5f * x0n * (1.f + erff(x0n * 0.70710678118654752f));
    x1n = 0.5f * x1n * (1.f + erff(x1n * 0.70710678118654752f));

    bf16 ha, la, hb, lb_;
    split1(x0n, ha, la);
    split1(x1n, hb, lb_);
    __nv_bfloat162 th, tl;
    th.x = ha; th.y = hb; tl.x = la; tl.y = lb_;
    *(u32*)(oh + rowoff + c0)  = *(u32*)&th;
    *(u32*)(olo + rowoff + c0) = *(u32*)&tl;
}

// ===================== launch =====================
extern "C" void kernel_launch(void* const* d_in, const int* in_sizes, int n_in,
                              void* d_out, int out_size)
{
    const float* x0   = (const float*)d_in[0];
    const float* x1   = (const float*)d_in[1];
    const float* Wqk  = (const float*)d_in[2];
    const float* bqk  = (const float*)d_in[3];
    const float* Wv   = (const float*)d_in[4];
    const float* bv   = (const float*)d_in[5];
    const float* Wout = (const float*)d_in[6];
    const float* bout = (const float*)d_in[7];
    const float* W1   = (const float*)d_in[8];
    const float* b1   = (const float*)d_in[9];
    const float* ln_g = (const float*)d_in[10];
    const float* ln_b = (const float*)d_in[11];
    const float* W2   = (const float*)d_in[12];
    const float* b2   = (const float*)d_in[13];
    float* out = (float*)d_out;

    float *p_qk0, *p_qk1, *p_v0, *p_v1, *p_h0, *p_h1;
    bf16 *px0h, *px0l, *px1h, *px1l;
    bf16 *pm0h, *pm0l, *pm1h, *pm1l;
    bf16 *pp0h, *pp0l, *pp1h, *pp1l;
    bf16 *ph0h, *ph0l, *ph1h, *ph1l;
    bf16 *pWqkh, *pWqkl, *pWvh, *pWvl, *pWoth, *pWotl, *pW1h, *pW1l, *pW2h, *pW2l;

    cudaGetSymbolAddress((void**)&p_qk0, g_qk0);
    cudaGetSymbolAddress((void**)&p_qk1, g_qk1);
    cudaGetSymbolAddress((void**)&p_v0,  g_v0);
    cudaGetSymbolAddress((void**)&p_v1,  g_v1);
    cudaGetSymbolAddress((void**)&p_h0,  g_h0);
    cudaGetSymbolAddress((void**)&p_h1,  g_h1);
    cudaGetSymbolAddress((void**)&px0h, g_x0h); cudaGetSymbolAddress((void**)&px0l, g_x0l);
    cudaGetSymbolAddress((void**)&px1h, g_x1h); cudaGetSymbolAddress((void**)&px1l, g_x1l);
    cudaGetSymbolAddress((void**)&pm0h, g_m0h); cudaGetSymbolAddress((void**)&pm0l, g_m0l);
    cudaGetSymbolAddress((void**)&pm1h, g_m1h); cudaGetSymbolAddress((void**)&pm1l, g_m1l);
    cudaGetSymbolAddress((void**)&pp0h, g_p0h); cudaGetSymbolAddress((void**)&pp0l, g_p0l);
    cudaGetSymbolAddress((void**)&pp1h, g_p1h); cudaGetSymbolAddress((void**)&pp1l, g_p1l);
    cudaGetSymbolAddress((void**)&ph0h, g_h0h); cudaGetSymbolAddress((void**)&ph0l, g_h0l);
    cudaGetSymbolAddress((void**)&ph1h, g_h1h); cudaGetSymbolAddress((void**)&ph1l, g_h1l);
    cudaGetSymbolAddress((void**)&pWqkh, g_Wqkh); cudaGetSymbolAddress((void**)&pWqkl, g_Wqkl);
    cudaGetSymbolAddress((void**)&pWvh,  g_Wvh);  cudaGetSymbolAddress((void**)&pWvl,  g_Wvl);
    cudaGetSymbolAddress((void**)&pWoth, g_Woth); cudaGetSymbolAddress((void**)&pWotl, g_Wotl);
    cudaGetSymbolAddress((void**)&pW1h,  g_W1h);  cudaGetSymbolAddress((void**)&pW1l,  g_W1l);
    cudaGetSymbolAddress((void**)&pW2h,  g_W2h);  cudaGetSymbolAddress((void**)&pW2l,  g_W2l);

    const int FLASH_SMEM = FLASH_SMEM_FLOATS * sizeof(float);
    cudaFuncSetAttribute(flash_kernel,
                         cudaFuncAttributeMaxDynamicSharedMemorySize, FLASH_SMEM);
    cudaFuncSetAttribute(mma_gemm,
                         cudaFuncAttributeMaxDynamicSharedMemorySize, MG_SMEM);

    const float qscale = 0.35355339059327373f; // 64^-0.25

    // ---- conversions ----
    split_kernel<<<RR * CC / 1024, 256>>>(x0, px0h, px0l, RR * CC);
    split_kernel<<<RR * CC / 1024, 256>>>(x1, px1h, px1l, RR * CC);
    wsplit_kernel<<<dim3(CC/32, CC/32), dim3(32,8)>>>(Wqk,  pWqkh, pWqkl, CC, CC);
    wsplit_kernel<<<dim3(CC/32, CC/32), dim3(32,8)>>>(Wv,   pWvh,  pWvl,  CC, CC);
    wsplit_kernel<<<dim3(CC/32, CC/32), dim3(32,8)>>>(Wout, pWoth, pWotl, CC, CC);
    wsplit_kernel<<<dim3(C2/32, C2/32), dim3(32,8)>>>(W1,   pW1h,  pW1l,  C2, C2);
    wsplit_kernel<<<dim3(CC/32, C2/32), dim3(32,8)>>>(W2,   pW2h,  pW2l,  C2, CC);

    dim3 g256(2, 128);
    dim3 g512(4, 128);

    // ---- QK / V projections -> head-layout f32 ----
    mma_gemm<<<g256, 256, MG_SMEM>>>(px0h, px0l, CC, nullptr, nullptr, 0,
        pWqkh, pWqkl, bqk, nullptr, p_qk0, nullptr, nullptr, CC, qscale, 1);
    mma_gemm<<<g256, 256, MG_SMEM>>>(px1h, px1l, CC, nullptr, nullptr, 0,
        pWqkh, pWqkl, bqk, nullptr, p_qk1, nullptr, nullptr, CC, qscale, 1);
    mma_gemm<<<g256, 256, MG_SMEM>>>(px0h, px0l, CC, nullptr, nullptr, 0,
        pWvh, pWvl, bv, nullptr, p_v0, nullptr, nullptr, CC, 1.f, 1);
    mma_gemm<<<g256, 256, MG_SMEM>>>(px1h, px1l, CC, nullptr, nullptr, 0,
        pWvh, pWvl, bv, nullptr, p_v1, nullptr, nullptr, CC, 1.f, 1);

    // ---- dual flash attention -> split bf16 merged ----
    dim3 fg(LL / 128, BB * HH, 2);
    flash_kernel<<<fg, 256, FLASH_SMEM>>>(p_qk0, p_qk1, p_v0, p_v1,
                                          pm0h, pm0l, pm1h, pm1l);

    // ---- output projection -> split bf16 ----
    mma_gemm<<<g256, 256, MG_SMEM>>>(pm0h, pm0l, CC, nullptr, nullptr, 0,
        pWoth, pWotl, bout, nullptr, nullptr, pp0h, pp0l, CC, 1.f, 2);
    mma_gemm<<<g256, 256, MG_SMEM>>>(pm1h, pm1l, CC, nullptr, nullptr, 0,
        pWoth, pWotl, bout, nullptr, nullptr, pp1h, pp1l, CC, 1.f, 2);

    // ---- FFN-1 on virtual concat([x, p]) -> f32 ----
    mma_gemm<<<g512, 256, MG_SMEM>>>(px0h, px0l, CC, pp0h, pp0l, CC,
        pW1h, pW1l, b1, nullptr, p_h0, nullptr, nullptr, C2, 1.f, 0);
    mma_gemm<<<g512, 256, MG_SMEM>>>(px1h, px1l, CC, pp1h, pp1l, CC,
        pW1h, pW1l, b1, nullptr, p_h1, nullptr, nullptr, C2, 1.f, 0);

    // ---- LayerNorm + GELU -> split bf16 ----
    dim3 lg(RR, 2);
    ln_gelu_kernel<<<lg, 256>>>(p_h0, p_h1, ph0h, ph0l, ph1h, ph1l, ln_g, ln_b);

    // ---- FFN-2 + residual -> outputs ----
    mma_gemm<<<g256, 256, MG_SMEM>>>(ph0h, ph0l, C2, nullptr, nullptr, 0,
        pW2h, pW2l, b2, x0, out, nullptr, nullptr, CC, 1.f, 0);
    mma_gemm<<<g256, 256, MG_SMEM>>>(ph1h, ph1l, C2, nullptr, nullptr, 0,
        pW2h, pW2l, b2, x1, out + (size_t)RR * CC, nullptr, nullptr, CC, 1.f, 0);
}

// round 6
// speedup vs baseline: 1.7379x; 1.7379x over previous
#include <cuda_runtime.h>
#include <cuda_bf16.h>
#include <math.h>
#include <stdint.h>

#define BB 8
#define LL 2048
#define CC 256
#define HH 4
#define DDIM 64
#define RR (BB*LL)
#define C2 (2*CC)

typedef unsigned long long u64;
typedef unsigned int u32;
typedef __nv_bfloat16 bf16;

__device__ __forceinline__ void split1(float x, bf16& h_, bf16& l_) {
    h_ = __float2bfloat16(x);
    l_ = __float2bfloat16(x - __bfloat162float(h_));
}
__device__ __forceinline__ void splitpack(float a, float b, u32& hi, u32& lo) {
    bf16 ah, al, bh_, bl_;
    split1(a, ah, al); split1(b, bh_, bl_);
    __nv_bfloat162 th, tl;
    th.x = ah; th.y = bh_; tl.x = al; tl.y = bl_;
    hi = *(u32*)&th; lo = *(u32*)&tl;
}
__device__ __forceinline__ u32 smem_u32(const void* p) {
    u32 a;
    asm("{ .reg .u64 t; cvta.to.shared.u64 t, %1; cvt.u32.u64 %0, t; }"
        : "=r"(a) : "l"(p));
    return a;
}
__device__ __forceinline__ void ldsm4(u32 addr, u32& r0, u32& r1, u32& r2, u32& r3) {
    asm volatile("ldmatrix.sync.aligned.m8n8.x4.shared.b16 {%0,%1,%2,%3}, [%4];"
                 : "=r"(r0), "=r"(r1), "=r"(r2), "=r"(r3) : "r"(addr));
}
__device__ __forceinline__ void ldsm4t(u32 addr, u32& r0, u32& r1, u32& r2, u32& r3) {
    asm volatile("ldmatrix.sync.aligned.m8n8.x4.trans.shared.b16 {%0,%1,%2,%3}, [%4];"
                 : "=r"(r0), "=r"(r1), "=r"(r2), "=r"(r3) : "r"(addr));
}
__device__ __forceinline__ void mma_bf16(float* c, const u32* a, const u32* b) {
    asm volatile(
        "mma.sync.aligned.m16n8k16.row.col.f32.bf16.bf16.f32 "
        "{%0,%1,%2,%3},{%4,%5,%6,%7},{%8,%9},{%0,%1,%2,%3};"
        : "+f"(c[0]), "+f"(c[1]), "+f"(c[2]), "+f"(c[3])
        : "r"(a[0]), "r"(a[1]), "r"(a[2]), "r"(a[3]), "r"(b[0]), "r"(b[1]));
}

// ===================== scratch =====================
__device__ float g_h0 [RR*C2];
__device__ float g_h1 [RR*C2];

__device__ bf16 g_x0h[RR*CC], g_x0l[RR*CC], g_x1h[RR*CC], g_x1l[RR*CC];
__device__ bf16 g_m0h[RR*CC], g_m0l[RR*CC], g_m1h[RR*CC], g_m1l[RR*CC];
__device__ bf16 g_p0h[RR*CC], g_p0l[RR*CC], g_p1h[RR*CC], g_p1l[RR*CC];
__device__ bf16 g_h0h[RR*C2], g_h0l[RR*C2], g_h1h[RR*C2], g_h1l[RR*C2];

__device__ bf16 g_qk0h[BB*HH*LL*DDIM], g_qk0l[BB*HH*LL*DDIM];
__device__ bf16 g_qk1h[BB*HH*LL*DDIM], g_qk1l[BB*HH*LL*DDIM];
__device__ bf16 g_v0h [BB*HH*LL*DDIM], g_v0l [BB*HH*LL*DDIM];
__device__ bf16 g_v1h [BB*HH*LL*DDIM], g_v1l [BB*HH*LL*DDIM];

__device__ bf16 g_Wqkh[CC*CC], g_Wqkl[CC*CC];
__device__ bf16 g_Wvh [CC*CC], g_Wvl [CC*CC];
__device__ bf16 g_Woth[CC*CC], g_Wotl[CC*CC];
__device__ bf16 g_W1h [C2*C2], g_W1l [C2*C2];
__device__ bf16 g_W2h [CC*C2], g_W2l [CC*C2];

// ===================== split f32 -> bf16 hi/lo =====================
__global__ __launch_bounds__(256) void split_kernel(
    const float* __restrict__ x, bf16* __restrict__ hi, bf16* __restrict__ lo, int n)
{
    int i = (blockIdx.x * 256 + threadIdx.x) * 4;
    if (i >= n) return;
    float4 v = *(const float4*)(x + i);
    uint2 uh, ul;
    splitpack(v.x, v.y, uh.x, ul.x);
    splitpack(v.z, v.w, uh.y, ul.y);
    *(uint2*)(hi + i) = uh;
    *(uint2*)(lo + i) = ul;
}

// ===================== transpose W [K,N] -> split [N,K] =====================
__global__ __launch_bounds__(256) void wsplit_kernel(
    const float* __restrict__ W, bf16* __restrict__ hi, bf16* __restrict__ lo,
    int K, int N)
{
    __shared__ float t[32][33];
    int nb = blockIdx.x * 32, kb = blockIdx.y * 32;
    int tx = threadIdx.x, ty0 = threadIdx.y;
    #pragma unroll
    for (int r = 0; r < 4; r++) {
        int ty = ty0 + r * 8;
        t[ty][tx] = W[(size_t)(kb + ty) * N + nb + tx];
    }
    __syncthreads();
    #pragma unroll
    for (int r = 0; r < 4; r++) {
        int ty = ty0 + r * 8;
        float v = t[tx][ty];
        bf16 h_, l_;
        split1(v, h_, l_);
        size_t o = (size_t)(nb + ty) * K + kb + tx;
        hi[o] = h_; lo[o] = l_;
    }
}

// ===================== mma.sync split-bf16 GEMM =====================
// mode: 0 = f32 out (+res), 2 = split bf16 out, 3 = split bf16 head-layout
#define MG_SMEM (64*1024 + 128)

__global__ __launch_bounds__(256, 2) void mma_gemm(
    const bf16* __restrict__ a0h, const bf16* __restrict__ a0l, int K0,
    const bf16* __restrict__ a1h, const bf16* __restrict__ a1l, int K1,
    const bf16* __restrict__ bh, const bf16* __restrict__ bl,
    const float* __restrict__ bias,
    const float* __restrict__ res,
    float* __restrict__ outf,
    bf16* __restrict__ outh, bf16* __restrict__ outl,
    int N, float scale, int mode)
{
    extern __shared__ char dsm[];
    u32 sb0 = smem_u32(dsm);
    u32 sb  = (sb0 + 127) & ~127u;
    char* smp = dsm + (sb - sb0);

    const int tid  = threadIdx.x;
    const int wid  = tid >> 5;
    const int lane = tid & 31;

    const int m0 = blockIdx.y * 128;
    const int n0 = blockIdx.x * 128;
    const int KB = K0 + K1;
    const int nc0 = K0 >> 6;
    const int nc  = KB >> 6;

    const int wm = (wid >> 2) * 64;
    const int wn = (wid & 3) * 32;

    const u32 sAh = sb;
    const u32 sAl = sb + 16384;
    const u32 sBh = sb + 32768;
    const u32 sBl = sb + 49152;

    float acc[4][4][4];
    #pragma unroll
    for (int i = 0; i < 4; i++)
        #pragma unroll
        for (int j = 0; j < 4; j++)
            #pragma unroll
            for (int t = 0; t < 4; t++) acc[i][j][t] = 0.f;

    const int ld_row = tid >> 3;
    const int ld_ch  = tid & 7;

    for (int c = 0; c < nc; c++) {
        __syncthreads();
        const bf16 *Ah, *Al;
        int astr, koff;
        if (c < nc0) { Ah = a0h; Al = a0l; astr = K0; koff = c << 6; }
        else         { Ah = a1h; Al = a1l; astr = K1; koff = (c - nc0) << 6; }
        const int koffB = c << 6;

        #pragma unroll
        for (int i = 0; i < 4; i++) {
            int row = ld_row + i * 32;
            u32 off = (u32)(row * 128 + ((ld_ch ^ (row & 7)) << 4));
            *(uint4*)(smp + off) =
                *(const uint4*)(Ah + (size_t)(m0 + row) * astr + koff + ld_ch * 8);
            *(uint4*)(smp + 16384 + off) =
                *(const uint4*)(Al + (size_t)(m0 + row) * astr + koff + ld_ch * 8);
            *(uint4*)(smp + 32768 + off) =
                *(const uint4*)(bh + (size_t)(n0 + row) * KB + koffB + ld_ch * 8);
            *(uint4*)(smp + 49152 + off) =
                *(const uint4*)(bl + (size_t)(n0 + row) * KB + koffB + ld_ch * 8);
        }
        __syncthreads();

        #pragma unroll
        for (int ks = 0; ks < 4; ks++) {
            const int cidx = ks * 2 + (lane >> 4);
            u32 bfh[4][2], bfl[4][2];
            #pragma unroll
            for (int g = 0; g < 2; g++) {
                int rb = wn + g * 16 + (lane & 15);
                u32 off = (u32)(rb * 128 + ((cidx ^ (rb & 7)) << 4));
                u32 r0, r1, r2, r3;
                ldsm4(sBh + off, r0, r1, r2, r3);
                bfh[2*g][0] = r0; bfh[2*g][1] = r2;
                bfh[2*g+1][0] = r1; bfh[2*g+1][1] = r3;
                ldsm4(sBl + off, r0, r1, r2, r3);
                bfl[2*g][0] = r0; bfl[2*g][1] = r2;
                bfl[2*g+1][0] = r1; bfl[2*g+1][1] = r3;
            }
            u32 af[4][4];
            #pragma unroll
            for (int mi = 0; mi < 4; mi++) {
                int ra = wm + mi * 16 + (lane & 15);
                u32 off = (u32)(ra * 128 + ((cidx ^ (ra & 7)) << 4));
                ldsm4(sAh + off, af[mi][0], af[mi][1], af[mi][2], af[mi][3]);
            }
            #pragma unroll
            for (int mi = 0; mi < 4; mi++)
                #pragma unroll
                for (int nj = 0; nj < 4; nj++)
                    mma_bf16(acc[mi][nj], af[mi], bfh[nj]);
            #pragma unroll
            for (int mi = 0; mi < 4; mi++)
                #pragma unroll
                for (int nj = 0; nj < 4; nj++)
                    mma_bf16(acc[mi][nj], af[mi], bfl[nj]);
            #pragma unroll
            for (int mi = 0; mi < 4; mi++) {
                int ra = wm + mi * 16 + (lane & 15);
                u32 off = (u32)(ra * 128 + ((cidx ^ (ra & 7)) << 4));
                ldsm4(sAl + off, af[mi][0], af[mi][1], af[mi][2], af[mi][3]);
            }
            #pragma unroll
            for (int mi = 0; mi < 4; mi++)
                #pragma unroll
                for (int nj = 0; nj < 4; nj++)
                    mma_bf16(acc[mi][nj], af[mi], bfh[nj]);
        }
    }

    const int lr = lane >> 2;
    const int lc = (lane & 3) * 2;
    #pragma unroll
    for (int mi = 0; mi < 4; mi++) {
        #pragma unroll
        for (int half = 0; half < 2; half++) {
            int r = m0 + wm + mi * 16 + lr + half * 8;
            #pragma unroll
            for (int nj = 0; nj < 4; nj++) {
                int col = n0 + wn + nj * 8 + lc;
                float2 bv = *(const float2*)(bias + col);
                float v0 = (acc[mi][nj][half * 2]     + bv.x) * scale;
                float v1 = (acc[mi][nj][half * 2 + 1] + bv.y) * scale;
                if (mode == 0) {
                    size_t o = (size_t)r * N + col;
                    if (res) {
                        float2 rv = *(const float2*)(res + o);
                        v0 += rv.x; v1 += rv.y;
                    }
                    *(float2*)(outf + o) = make_float2(v0, v1);
                } else if (mode == 2) {
                    size_t o = (size_t)r * N + col;
                    u32 hi, lo;
                    splitpack(v0, v1, hi, lo);
                    *(u32*)(outh + o) = hi;
                    *(u32*)(outl + o) = lo;
                } else { // mode 3: head layout split
                    int b_ = r >> 11, l = r & 2047;
                    int h  = col >> 6, d = col & 63;
                    size_t o = (((size_t)(b_ * HH + h)) * LL + l) * DDIM + d;
                    u32 hi, lo;
                    splitpack(v0, v1, hi, lo);
                    *(u32*)(outh + o) = hi;
                    *(u32*)(outl + o) = lo;
                }
            }
        }
    }
}

// ===================== flash attention via mma.sync =====================
// grid (16, 32, 2), 256 thr. Block: 128 q-rows, K-tiles of 128.
// Warp w owns q-rows q0+w*16..+15. S acc = 16 n8-tiles (full 128 kcols).
// P stays in registers (C-frag == A-frag layout). V B-frags via trans-ldsm.
#define FK_SMEM (6*16384 + 128)

__global__ __launch_bounds__(256, 1) void flash_mma(
    const bf16* __restrict__ qk0h, const bf16* __restrict__ qk0l,
    const bf16* __restrict__ qk1h, const bf16* __restrict__ qk1l,
    const bf16* __restrict__ v0h,  const bf16* __restrict__ v0l,
    const bf16* __restrict__ v1h,  const bf16* __restrict__ v1l,
    bf16* __restrict__ m0h, bf16* __restrict__ m0l,
    bf16* __restrict__ m1h, bf16* __restrict__ m1l)
{
    extern __shared__ char dsm[];
    u32 sb0 = smem_u32(dsm);
    u32 sb  = (sb0 + 127) & ~127u;
    char* smp = dsm + (sb - sb0);

    const int dir = blockIdx.z;
    const bf16* qh = dir ? qk1h : qk0h;
    const bf16* ql = dir ? qk1l : qk0l;
    const bf16* kh = dir ? qk0h : qk1h;
    const bf16* kl = dir ? qk0l : qk1l;
    const bf16* vh = dir ? v0h : v1h;
    const bf16* vl = dir ? v0l : v1l;
    bf16* ohp = dir ? m1h : m0h;
    bf16* olp = dir ? m1l : m0l;

    const int bh = blockIdx.y;
    const size_t base = (size_t)bh * LL * DDIM;
    const int q0 = blockIdx.x * 128;
    const int tid  = threadIdx.x;
    const int wid  = tid >> 5;
    const int lane = tid & 31;
    const int g  = lane >> 2;
    const int t4 = lane & 3;
    const int rb = lane & 15;
    const int chsel = lane >> 4;

    const u32 sQh = sb;
    const u32 sQl = sb + 16384;
    const u32 sKh = sb + 32768;
    const u32 sKl = sb + 49152;
    const u32 sVh = sb + 65536;
    const u32 sVl = sb + 81920;

    // load Q tile (128x64, hi/lo), swizzled rows of 128B
    #pragma unroll
    for (int rep = 0; rep < 4; rep++) {
        int idx = rep * 256 + tid;
        int row = idx >> 3, ch = idx & 7;
        u32 soff = (u32)(row * 128 + ((ch ^ (row & 7)) << 4));
        size_t goff = base + (size_t)(q0 + row) * DDIM + ch * 8;
        *(uint4*)(smp + soff)         = *(const uint4*)(qh + goff);
        *(uint4*)(smp + 16384 + soff) = *(const uint4*)(ql + goff);
    }
    __syncthreads();

    // Q fragments (per warp 16 rows, 4 k16 steps, hi+lo)
    u32 qfh[4][4], qfl[4][4];
    {
        int qr = wid * 16 + rb;
        #pragma unroll
        for (int ks = 0; ks < 4; ks++) {
            int chunk = ks * 2 + chsel;
            u32 off = (u32)(qr * 128 + ((chunk ^ (qr & 7)) << 4));
            ldsm4(sQh + off, qfh[ks][0], qfh[ks][1], qfh[ks][2], qfh[ks][3]);
            ldsm4(sQl + off, qfl[ks][0], qfl[ks][1], qfl[ks][2], qfl[ks][3]);
        }
    }

    float mrow0 = -1e30f, mrow1 = -1e30f, lrow0 = 0.f, lrow1 = 0.f;
    float oacc[8][4];
    #pragma unroll
    for (int dt = 0; dt < 8; dt++)
        #pragma unroll
        for (int t = 0; t < 4; t++) oacc[dt][t] = 0.f;

    for (int it = 0; it < 16; it++) {
        __syncthreads();
        const int k0 = it * 128;
        #pragma unroll
        for (int rep = 0; rep < 4; rep++) {
            int idx = rep * 256 + tid;
            int row = idx >> 3, ch = idx & 7;
            u32 soff = (u32)(row * 128 + ((ch ^ (row & 7)) << 4));
            size_t goff = base + (size_t)(k0 + row) * DDIM + ch * 8;
            *(uint4*)(smp + 32768 + soff) = *(const uint4*)(kh + goff);
            *(uint4*)(smp + 49152 + soff) = *(const uint4*)(kl + goff);
            *(uint4*)(smp + 65536 + soff) = *(const uint4*)(vh + goff);
            *(uint4*)(smp + 81920 + soff) = *(const uint4*)(vl + goff);
        }
        __syncthreads();

        // ---- S = Q K^T (3-pass split) ----
        float acc[16][4];
        #pragma unroll
        for (int nt = 0; nt < 16; nt++)
            #pragma unroll
            for (int t = 0; t < 4; t++) acc[nt][t] = 0.f;

        #pragma unroll
        for (int ks = 0; ks < 4; ks++) {
            int chunk = ks * 2 + chsel;
            u32 bf[16][2];
            #pragma unroll
            for (int gg = 0; gg < 8; gg++) {
                int rr = gg * 16 + rb;
                u32 off = (u32)(rr * 128 + ((chunk ^ (rr & 7)) << 4));
                u32 r0, r1, r2, r3;
                ldsm4(sKh + off, r0, r1, r2, r3);
                bf[2*gg][0] = r0; bf[2*gg][1] = r2;
                bf[2*gg+1][0] = r1; bf[2*gg+1][1] = r3;
            }
            #pragma unroll
            for (int nt = 0; nt < 16; nt++) mma_bf16(acc[nt], qfh[ks], bf[nt]);
            #pragma unroll
            for (int nt = 0; nt < 16; nt++) mma_bf16(acc[nt], qfl[ks], bf[nt]);
            #pragma unroll
            for (int gg = 0; gg < 8; gg++) {
                int rr = gg * 16 + rb;
                u32 off = (u32)(rr * 128 + ((chunk ^ (rr & 7)) << 4));
                u32 r0, r1, r2, r3;
                ldsm4(sKl + off, r0, r1, r2, r3);
                bf[2*gg][0] = r0; bf[2*gg][1] = r2;
                bf[2*gg+1][0] = r1; bf[2*gg+1][1] = r3;
            }
            #pragma unroll
            for (int nt = 0; nt < 16; nt++) mma_bf16(acc[nt], qfh[ks], bf[nt]);
        }

        // ---- online softmax (rows g and g+8; 4 lanes/row via shfl) ----
        float mx0 = -1e30f, mx1 = -1e30f;
        #pragma unroll
        for (int nt = 0; nt < 16; nt++) {
            mx0 = fmaxf(mx0, fmaxf(acc[nt][0], acc[nt][1]));
            mx1 = fmaxf(mx1, fmaxf(acc[nt][2], acc[nt][3]));
        }
        mx0 = fmaxf(mx0, __shfl_xor_sync(0xffffffffu, mx0, 1));
        mx0 = fmaxf(mx0, __shfl_xor_sync(0xffffffffu, mx0, 2));
        mx1 = fmaxf(mx1, __shfl_xor_sync(0xffffffffu, mx1, 1));
        mx1 = fmaxf(mx1, __shfl_xor_sync(0xffffffffu, mx1, 2));
        float mn0 = fmaxf(mrow0, mx0), mn1 = fmaxf(mrow1, mx1);
        float al0 = __expf(mrow0 - mn0), al1 = __expf(mrow1 - mn1);
        mrow0 = mn0; mrow1 = mn1;
        float s0 = 0.f, s1 = 0.f;
        #pragma unroll
        for (int nt = 0; nt < 16; nt++) {
            acc[nt][0] = __expf(acc[nt][0] - mn0);
            acc[nt][1] = __expf(acc[nt][1] - mn0);
            acc[nt][2] = __expf(acc[nt][2] - mn1);
            acc[nt][3] = __expf(acc[nt][3] - mn1);
            s0 += acc[nt][0] + acc[nt][1];
            s1 += acc[nt][2] + acc[nt][3];
        }
        s0 += __shfl_xor_sync(0xffffffffu, s0, 1);
        s0 += __shfl_xor_sync(0xffffffffu, s0, 2);
        s1 += __shfl_xor_sync(0xffffffffu, s1, 1);
        s1 += __shfl_xor_sync(0xffffffffu, s1, 2);
        lrow0 = lrow0 * al0 + s0;
        lrow1 = lrow1 * al1 + s1;
        #pragma unroll
        for (int dt = 0; dt < 8; dt++) {
            oacc[dt][0] *= al0; oacc[dt][1] *= al0;
            oacc[dt][2] *= al1; oacc[dt][3] *= al1;
        }

        // ---- pack P (C-frag -> A-frag, split hi/lo) ----
        u32 ph[8][4], plo[8][4];
        #pragma unroll
        for (int kb = 0; kb < 8; kb++) {
            splitpack(acc[2*kb][0],   acc[2*kb][1],   ph[kb][0], plo[kb][0]);
            splitpack(acc[2*kb][2],   acc[2*kb][3],   ph[kb][1], plo[kb][1]);
            splitpack(acc[2*kb+1][0], acc[2*kb+1][1], ph[kb][2], plo[kb][2]);
            splitpack(acc[2*kb+1][2], acc[2*kb+1][3], ph[kb][3], plo[kb][3]);
        }

        // ---- O += P V (3-pass split; V B-frags via trans ldsm) ----
        #pragma unroll
        for (int kb = 0; kb < 8; kb++) {
            int rr = kb * 16 + rb;
            u32 vf[8][2];
            #pragma unroll
            for (int dg = 0; dg < 4; dg++) {
                int chunk = dg * 2 + chsel;
                u32 off = (u32)(rr * 128 + ((chunk ^ (rr & 7)) << 4));
                u32 r0, r1, r2, r3;
                ldsm4t(sVh + off, r0, r1, r2, r3);
                vf[2*dg][0] = r0; vf[2*dg][1] = r1;
                vf[2*dg+1][0] = r2; vf[2*dg+1][1] = r3;
            }
            #pragma unroll
            for (int dt = 0; dt < 8; dt++) mma_bf16(oacc[dt], ph[kb],  vf[dt]);
            #pragma unroll
            for (int dt = 0; dt < 8; dt++) mma_bf16(oacc[dt], plo[kb], vf[dt]);
            #pragma unroll
            for (int dg = 0; dg < 4; dg++) {
                int chunk = dg * 2 + chsel;
                u32 off = (u32)(rr * 128 + ((chunk ^ (rr & 7)) << 4));
                u32 r0, r1, r2, r3;
                ldsm4t(sVl + off, r0, r1, r2, r3);
                vf[2*dg][0] = r0; vf[2*dg][1] = r1;
                vf[2*dg+1][0] = r2; vf[2*dg+1][1] = r3;
            }
            #pragma unroll
            for (int dt = 0; dt < 8; dt++) mma_bf16(oacc[dt], ph[kb], vf[dt]);
        }
    }

    // ---- epilogue: normalize, split-store merged (B,L,C) ----
    float inv0 = 1.f / lrow0, inv1 = 1.f / lrow1;
    int r0g = q0 + wid * 16 + g;
    int bb = bh >> 2, hh = bh & 3;
    #pragma unroll
    for (int dt = 0; dt < 8; dt++) {
        int col = hh * DDIM + dt * 8 + t4 * 2;
        size_t o0 = (size_t)(bb * LL + r0g) * CC + col;
        size_t o1 = (size_t)(bb * LL + r0g + 8) * CC + col;
        u32 hi, lo;
        splitpack(oacc[dt][0] * inv0, oacc[dt][1] * inv0, hi, lo);
        *(u32*)(ohp + o0) = hi; *(u32*)(olp + o0) = lo;
        splitpack(oacc[dt][2] * inv1, oacc[dt][3] * inv1, hi, lo);
        *(u32*)(ohp + o1) = hi; *(u32*)(olp + o1) = lo;
    }
}

// ===================== LayerNorm + exact GELU -> split bf16 =====================
__global__ __launch_bounds__(256) void ln_gelu_kernel(
    const float* __restrict__ h0, const float* __restrict__ h1,
    bf16* __restrict__ h0h, bf16* __restrict__ h0l,
    bf16* __restrict__ h1h, bf16* __restrict__ h1l,
    const float* __restrict__ g, const float* __restrict__ bta)
{
    const float* hp = blockIdx.y ? h1 : h0;
    bf16* oh = blockIdx.y ? h1h : h0h;
    bf16* olo = blockIdx.y ? h1l : h0l;
    const size_t rowoff = (size_t)blockIdx.x * C2;
    const int tid = threadIdx.x;
    const int lane = tid & 31, wid = tid >> 5;

    float2 v = *(const float2*)&hp[rowoff + tid * 2];
    float s  = v.x + v.y;
    float sq = v.x * v.x + v.y * v.y;
    #pragma unroll
    for (int off = 16; off; off >>= 1) {
        s  += __shfl_xor_sync(0xffffffffu, s,  off);
        sq += __shfl_xor_sync(0xffffffffu, sq, off);
    }
    __shared__ float rs[8], rq[8];
    if (lane == 0) { rs[wid] = s; rq[wid] = sq; }
    __syncthreads();
    if (wid == 0) {
        s  = (lane < 8) ? rs[lane] : 0.f;
        sq = (lane < 8) ? rq[lane] : 0.f;
        #pragma unroll
        for (int off = 4; off; off >>= 1) {
            s  += __shfl_xor_sync(0xffffffffu, s,  off);
            sq += __shfl_xor_sync(0xffffffffu, sq, off);
        }
        if (lane == 0) { rs[0] = s; rq[0] = sq; }
    }
    __syncthreads();
    float mean = rs[0] * (1.f / 512.f);
    float var  = rq[0] * (1.f / 512.f) - mean * mean;
    float rstd = rsqrtf(var + 1e-5f);

    int c0 = tid * 2;
    float x0n = (v.x - mean) * rstd * g[c0]     + bta[c0];
    float x1n = (v.y - mean) * rstd * g[c0 + 1] + bta[c0 + 1];
    x0n = 0.5f * x0n * (1.f + erff(x0n * 0.70710678118654752f));
    x1n = 0.5f * x1n * (1.f + erff(x1n * 0.70710678118654752f));

    u32 hi, lo;
    splitpack(x0n, x1n, hi, lo);
    *(u32*)(oh + rowoff + c0)  = hi;
    *(u32*)(olo + rowoff + c0) = lo;
}

// ===================== launch =====================
extern "C" void kernel_launch(void* const* d_in, const int* in_sizes, int n_in,
                              void* d_out, int out_size)
{
    const float* x0   = (const float*)d_in[0];
    const float* x1   = (const float*)d_in[1];
    const float* Wqk  = (const float*)d_in[2];
    const float* bqk  = (const float*)d_in[3];
    const float* Wv   = (const float*)d_in[4];
    const float* bv   = (const float*)d_in[5];
    const float* Wout = (const float*)d_in[6];
    const float* bout = (const float*)d_in[7];
    const float* W1   = (const float*)d_in[8];
    const float* b1   = (const float*)d_in[9];
    const float* ln_g = (const float*)d_in[10];
    const float* ln_b = (const float*)d_in[11];
    const float* W2   = (const float*)d_in[12];
    const float* b2   = (const float*)d_in[13];
    float* out = (float*)d_out;

    float *p_h0, *p_h1;
    bf16 *px0h, *px0l, *px1h, *px1l;
    bf16 *pm0h, *pm0l, *pm1h, *pm1l;
    bf16 *pp0h, *pp0l, *pp1h, *pp1l;
    bf16 *ph0h, *ph0l, *ph1h, *ph1l;
    bf16 *pq0h, *pq0l, *pq1h, *pq1l, *pv0h, *pv0l, *pv1h, *pv1l;
    bf16 *pWqkh, *pWqkl, *pWvh, *pWvl, *pWoth, *pWotl, *pW1h, *pW1l, *pW2h, *pW2l;

    cudaGetSymbolAddress((void**)&p_h0,  g_h0);
    cudaGetSymbolAddress((void**)&p_h1,  g_h1);
    cudaGetSymbolAddress((void**)&px0h, g_x0h); cudaGetSymbolAddress((void**)&px0l, g_x0l);
    cudaGetSymbolAddress((void**)&px1h, g_x1h); cudaGetSymbolAddress((void**)&px1l, g_x1l);
    cudaGetSymbolAddress((void**)&pm0h, g_m0h); cudaGetSymbolAddress((void**)&pm0l, g_m0l);
    cudaGetSymbolAddress((void**)&pm1h, g_m1h); cudaGetSymbolAddress((void**)&pm1l, g_m1l);
    cudaGetSymbolAddress((void**)&pp0h, g_p0h); cudaGetSymbolAddress((void**)&pp0l, g_p0l);
    cudaGetSymbolAddress((void**)&pp1h, g_p1h); cudaGetSymbolAddress((void**)&pp1l, g_p1l);
    cudaGetSymbolAddress((void**)&ph0h, g_h0h); cudaGetSymbolAddress((void**)&ph0l, g_h0l);
    cudaGetSymbolAddress((void**)&ph1h, g_h1h); cudaGetSymbolAddress((void**)&ph1l, g_h1l);
    cudaGetSymbolAddress((void**)&pq0h, g_qk0h); cudaGetSymbolAddress((void**)&pq0l, g_qk0l);
    cudaGetSymbolAddress((void**)&pq1h, g_qk1h); cudaGetSymbolAddress((void**)&pq1l, g_qk1l);
    cudaGetSymbolAddress((void**)&pv0h, g_v0h);  cudaGetSymbolAddress((void**)&pv0l, g_v0l);
    cudaGetSymbolAddress((void**)&pv1h, g_v1h);  cudaGetSymbolAddress((void**)&pv1l, g_v1l);
    cudaGetSymbolAddress((void**)&pWqkh, g_Wqkh); cudaGetSymbolAddress((void**)&pWqkl, g_Wqkl);
    cudaGetSymbolAddress((void**)&pWvh,  g_Wvh);  cudaGetSymbolAddress((void**)&pWvl,  g_Wvl);
    cudaGetSymbolAddress((void**)&pWoth, g_Woth); cudaGetSymbolAddress((void**)&pWotl, g_Wotl);
    cudaGetSymbolAddress((void**)&pW1h,  g_W1h);  cudaGetSymbolAddress((void**)&pW1l,  g_W1l);
    cudaGetSymbolAddress((void**)&pW2h,  g_W2h);  cudaGetSymbolAddress((void**)&pW2l,  g_W2l);

    cudaFuncSetAttribute(mma_gemm,
                         cudaFuncAttributeMaxDynamicSharedMemorySize, MG_SMEM);
    cudaFuncSetAttribute(flash_mma,
                         cudaFuncAttributeMaxDynamicSharedMemorySize, FK_SMEM);

    const float qscale = 0.35355339059327373f; // 64^-0.25

    split_kernel<<<RR * CC / 1024, 256>>>(x0, px0h, px0l, RR * CC);
    split_kernel<<<RR * CC / 1024, 256>>>(x1, px1h, px1l, RR * CC);
    wsplit_kernel<<<dim3(CC/32, CC/32), dim3(32,8)>>>(Wqk,  pWqkh, pWqkl, CC, CC);
    wsplit_kernel<<<dim3(CC/32, CC/32), dim3(32,8)>>>(Wv,   pWvh,  pWvl,  CC, CC);
    wsplit_kernel<<<dim3(CC/32, CC/32), dim3(32,8)>>>(Wout, pWoth, pWotl, CC, CC);
    wsplit_kernel<<<dim3(C2/32, C2/32), dim3(32,8)>>>(W1,   pW1h,  pW1l,  C2, C2);
    wsplit_kernel<<<dim3(CC/32, C2/32), dim3(32,8)>>>(W2,   pW2h,  pW2l,  C2, CC);

    dim3 g256(2, 128);
    dim3 g512(4, 128);

    // QK / V projections -> split bf16 head layout (mode 3)
    mma_gemm<<<g256, 256, MG_SMEM>>>(px0h, px0l, CC, nullptr, nullptr, 0,
        pWqkh, pWqkl, bqk, nullptr, nullptr, pq0h, pq0l, CC, qscale, 3);
    mma_gemm<<<g256, 256, MG_SMEM>>>(px1h, px1l, CC, nullptr, nullptr, 0,
        pWqkh, pWqkl, bqk, nullptr, nullptr, pq1h, pq1l, CC, qscale, 3);
    mma_gemm<<<g256, 256, MG_SMEM>>>(px0h, px0l, CC, nullptr, nullptr, 0,
        pWvh, pWvl, bv, nullptr, nullptr, pv0h, pv0l, CC, 1.f, 3);
    mma_gemm<<<g256, 256, MG_SMEM>>>(px1h, px1l, CC, nullptr, nullptr, 0,
        pWvh, pWvl, bv, nullptr, nullptr, pv1h, pv1l, CC, 1.f, 3);

    // dual flash attention (tensor-core) -> split bf16 merged
    dim3 fg(LL / 128, BB * HH, 2);
    flash_mma<<<fg, 256, FK_SMEM>>>(pq0h, pq0l, pq1h, pq1l,
                                    pv0h, pv0l, pv1h, pv1l,
                                    pm0h, pm0l, pm1h, pm1l);

    // output projection -> split bf16
    mma_gemm<<<g256, 256, MG_SMEM>>>(pm0h, pm0l, CC, nullptr, nullptr, 0,
        pWoth, pWotl, bout, nullptr, nullptr, pp0h, pp0l, CC, 1.f, 2);
    mma_gemm<<<g256, 256, MG_SMEM>>>(pm1h, pm1l, CC, nullptr, nullptr, 0,
        pWoth, pWotl, bout, nullptr, nullptr, pp1h, pp1l, CC, 1.f, 2);

    // FFN-1 on virtual concat([x, p]) -> f32
    mma_gemm<<<g512, 256, MG_SMEM>>>(px0h, px0l, CC, pp0h, pp0l, CC,
        pW1h, pW1l, b1, nullptr, p_h0, nullptr, nullptr, C2, 1.f, 0);
    mma_gemm<<<g512, 256, MG_SMEM>>>(px1h, px1l, CC, pp1h, pp1l, CC,
        pW1h, pW1l, b1, nullptr, p_h1, nullptr, nullptr, C2, 1.f, 0);

    // LayerNorm + GELU -> split bf16
    dim3 lg(RR, 2);
    ln_gelu_kernel<<<lg, 256>>>(p_h0, p_h1, ph0h, ph0l, ph1h, ph1l, ln_g, ln_b);

    // FFN-2 + residual -> outputs
    mma_gemm<<<g256, 256, MG_SMEM>>>(ph0h, ph0l, C2, nullptr, nullptr, 0,
        pW2h, pW2l, b2, x0, out, nullptr, nullptr, CC, 1.f, 0);
    mma_gemm<<<g256, 256, MG_SMEM>>>(ph1h, ph1l, C2, nullptr, nullptr, 0,
        pW2h, pW2l, b2, x1, out + (size_t)RR * CC, nullptr, nullptr, CC, 1.f, 0);
}

// round 7
// speedup vs baseline: 2.1102x; 1.2142x over previous
#include <cuda_runtime.h>
#include <cuda_bf16.h>
#include <cuda_fp16.h>
#include <math.h>
#include <stdint.h>

#define BB 8
#define LL 2048
#define CC 256
#define HH 4
#define DDIM 64
#define RR (BB*LL)
#define C2 (2*CC)

typedef unsigned long long u64;
typedef unsigned int u32;
typedef __nv_bfloat16 bf16;
typedef __half f16;

__device__ __forceinline__ void split1(float x, bf16& h_, bf16& l_) {
    h_ = __float2bfloat16(x);
    l_ = __float2bfloat16(x - __bfloat162float(h_));
}
__device__ __forceinline__ void splitpack(float a, float b, u32& hi, u32& lo) {
    bf16 ah, al, bh_, bl_;
    split1(a, ah, al); split1(b, bh_, bl_);
    __nv_bfloat162 th, tl;
    th.x = ah; th.y = bh_; tl.x = al; tl.y = bl_;
    hi = *(u32*)&th; lo = *(u32*)&tl;
}
__device__ __forceinline__ void splitpack_h(float a, float b, u32& hi, u32& lo) {
    f16 ah = __float2half_rn(a);
    f16 bh_ = __float2half_rn(b);
    f16 al = __float2half_rn(a - __half2float(ah));
    f16 bl_ = __float2half_rn(b - __half2float(bh_));
    __half2 th = __halves2half2(ah, bh_), tl = __halves2half2(al, bl_);
    hi = *(u32*)&th; lo = *(u32*)&tl;
}
__device__ __forceinline__ u32 pack_h2(float a, float b) {
    __half2 t = __halves2half2(__float2half_rn(a), __float2half_rn(b));
    return *(u32*)&t;
}
__device__ __forceinline__ u32 smem_u32(const void* p) {
    u32 a;
    asm("{ .reg .u64 t; cvta.to.shared.u64 t, %1; cvt.u32.u64 %0, t; }"
        : "=r"(a) : "l"(p));
    return a;
}
__device__ __forceinline__ void ldsm4(u32 addr, u32& r0, u32& r1, u32& r2, u32& r3) {
    asm volatile("ldmatrix.sync.aligned.m8n8.x4.shared.b16 {%0,%1,%2,%3}, [%4];"
                 : "=r"(r0), "=r"(r1), "=r"(r2), "=r"(r3) : "r"(addr));
}
__device__ __forceinline__ void ldsm4t(u32 addr, u32& r0, u32& r1, u32& r2, u32& r3) {
    asm volatile("ldmatrix.sync.aligned.m8n8.x4.trans.shared.b16 {%0,%1,%2,%3}, [%4];"
                 : "=r"(r0), "=r"(r1), "=r"(r2), "=r"(r3) : "r"(addr));
}
__device__ __forceinline__ void mma_bf16(float* c, const u32* a, const u32* b) {
    asm volatile(
        "mma.sync.aligned.m16n8k16.row.col.f32.bf16.bf16.f32 "
        "{%0,%1,%2,%3},{%4,%5,%6,%7},{%8,%9},{%0,%1,%2,%3};"
        : "+f"(c[0]), "+f"(c[1]), "+f"(c[2]), "+f"(c[3])
        : "r"(a[0]), "r"(a[1]), "r"(a[2]), "r"(a[3]), "r"(b[0]), "r"(b[1]));
}
__device__ __forceinline__ void mma_f16(float* c, const u32* a, const u32* b) {
    asm volatile(
        "mma.sync.aligned.m16n8k16.row.col.f32.f16.f16.f32 "
        "{%0,%1,%2,%3},{%4,%5,%6,%7},{%8,%9},{%0,%1,%2,%3};"
        : "+f"(c[0]), "+f"(c[1]), "+f"(c[2]), "+f"(c[3])
        : "r"(a[0]), "r"(a[1]), "r"(a[2]), "r"(a[3]), "r"(b[0]), "r"(b[1]));
}

// ===================== scratch =====================
__device__ float g_h0 [RR*C2];
__device__ float g_h1 [RR*C2];

__device__ bf16 g_x0h[RR*CC], g_x0l[RR*CC], g_x1h[RR*CC], g_x1l[RR*CC];
__device__ bf16 g_m0h[RR*CC], g_m0l[RR*CC], g_m1h[RR*CC], g_m1l[RR*CC];
__device__ bf16 g_p0h[RR*CC], g_p0l[RR*CC], g_p1h[RR*CC], g_p1l[RR*CC];
__device__ bf16 g_h0h[RR*C2], g_h0l[RR*C2], g_h1h[RR*C2], g_h1l[RR*C2];

__device__ f16 g_qk0h[BB*HH*LL*DDIM], g_qk0l[BB*HH*LL*DDIM];
__device__ f16 g_qk1h[BB*HH*LL*DDIM], g_qk1l[BB*HH*LL*DDIM];
__device__ f16 g_v0h [BB*HH*LL*DDIM], g_v0l [BB*HH*LL*DDIM];
__device__ f16 g_v1h [BB*HH*LL*DDIM], g_v1l [BB*HH*LL*DDIM];

__device__ bf16 g_Wqkh[CC*CC], g_Wqkl[CC*CC];
__device__ bf16 g_Wvh [CC*CC], g_Wvl [CC*CC];
__device__ bf16 g_Woth[CC*CC], g_Wotl[CC*CC];
__device__ bf16 g_W1h [C2*C2], g_W1l [C2*C2];
__device__ bf16 g_W2h [CC*C2], g_W2l [CC*C2];

// ===================== split f32 -> bf16 hi/lo =====================
__global__ __launch_bounds__(256) void split_kernel(
    const float* __restrict__ x, bf16* __restrict__ hi, bf16* __restrict__ lo, int n)
{
    int i = (blockIdx.x * 256 + threadIdx.x) * 4;
    if (i >= n) return;
    float4 v = *(const float4*)(x + i);
    uint2 uh, ul;
    splitpack(v.x, v.y, uh.x, ul.x);
    splitpack(v.z, v.w, uh.y, ul.y);
    *(uint2*)(hi + i) = uh;
    *(uint2*)(lo + i) = ul;
}

// ===================== transpose W [K,N] -> split [N,K] =====================
__global__ __launch_bounds__(256) void wsplit_kernel(
    const float* __restrict__ W, bf16* __restrict__ hi, bf16* __restrict__ lo,
    int K, int N)
{
    __shared__ float t[32][33];
    int nb = blockIdx.x * 32, kb = blockIdx.y * 32;
    int tx = threadIdx.x, ty0 = threadIdx.y;
    #pragma unroll
    for (int r = 0; r < 4; r++) {
        int ty = ty0 + r * 8;
        t[ty][tx] = W[(size_t)(kb + ty) * N + nb + tx];
    }
    __syncthreads();
    #pragma unroll
    for (int r = 0; r < 4; r++) {
        int ty = ty0 + r * 8;
        float v = t[tx][ty];
        bf16 h_, l_;
        split1(v, h_, l_);
        size_t o = (size_t)(nb + ty) * K + kb + tx;
        hi[o] = h_; lo[o] = l_;
    }
}

// ===================== mma.sync split-bf16 GEMM =====================
// mode: 0 = f32 out (+res), 2 = split bf16 out, 3 = split FP16 head-layout
#define MG_SMEM (64*1024 + 128)

__global__ __launch_bounds__(256, 2) void mma_gemm(
    const bf16* __restrict__ a0h, const bf16* __restrict__ a0l, int K0,
    const bf16* __restrict__ a1h, const bf16* __restrict__ a1l, int K1,
    const bf16* __restrict__ bh, const bf16* __restrict__ bl,
    const float* __restrict__ bias,
    const float* __restrict__ res,
    float* __restrict__ outf,
    bf16* __restrict__ outh, bf16* __restrict__ outl,
    f16* __restrict__ outfh, f16* __restrict__ outfl,
    int N, float scale, int mode)
{
    extern __shared__ char dsm[];
    u32 sb0 = smem_u32(dsm);
    u32 sb  = (sb0 + 127) & ~127u;
    char* smp = dsm + (sb - sb0);

    const int tid  = threadIdx.x;
    const int wid  = tid >> 5;
    const int lane = tid & 31;

    const int m0 = blockIdx.y * 128;
    const int n0 = blockIdx.x * 128;
    const int KB = K0 + K1;
    const int nc0 = K0 >> 6;
    const int nc  = KB >> 6;

    const int wm = (wid >> 2) * 64;
    const int wn = (wid & 3) * 32;

    const u32 sAh = sb;
    const u32 sAl = sb + 16384;
    const u32 sBh = sb + 32768;
    const u32 sBl = sb + 49152;

    float acc[4][4][4];
    #pragma unroll
    for (int i = 0; i < 4; i++)
        #pragma unroll
        for (int j = 0; j < 4; j++)
            #pragma unroll
            for (int t = 0; t < 4; t++) acc[i][j][t] = 0.f;

    const int ld_row = tid >> 3;
    const int ld_ch  = tid & 7;

    for (int c = 0; c < nc; c++) {
        __syncthreads();
        const bf16 *Ah, *Al;
        int astr, koff;
        if (c < nc0) { Ah = a0h; Al = a0l; astr = K0; koff = c << 6; }
        else         { Ah = a1h; Al = a1l; astr = K1; koff = (c - nc0) << 6; }
        const int koffB = c << 6;

        #pragma unroll
        for (int i = 0; i < 4; i++) {
            int row = ld_row + i * 32;
            u32 off = (u32)(row * 128 + ((ld_ch ^ (row & 7)) << 4));
            *(uint4*)(smp + off) =
                *(const uint4*)(Ah + (size_t)(m0 + row) * astr + koff + ld_ch * 8);
            *(uint4*)(smp + 16384 + off) =
                *(const uint4*)(Al + (size_t)(m0 + row) * astr + koff + ld_ch * 8);
            *(uint4*)(smp + 32768 + off) =
                *(const uint4*)(bh + (size_t)(n0 + row) * KB + koffB + ld_ch * 8);
            *(uint4*)(smp + 49152 + off) =
                *(const uint4*)(bl + (size_t)(n0 + row) * KB + koffB + ld_ch * 8);
        }
        __syncthreads();

        #pragma unroll
        for (int ks = 0; ks < 4; ks++) {
            const int cidx = ks * 2 + (lane >> 4);
            u32 bfh[4][2], bfl[4][2];
            #pragma unroll
            for (int g = 0; g < 2; g++) {
                int rb = wn + g * 16 + (lane & 15);
                u32 off = (u32)(rb * 128 + ((cidx ^ (rb & 7)) << 4));
                u32 r0, r1, r2, r3;
                ldsm4(sBh + off, r0, r1, r2, r3);
                bfh[2*g][0] = r0; bfh[2*g][1] = r2;
                bfh[2*g+1][0] = r1; bfh[2*g+1][1] = r3;
                ldsm4(sBl + off, r0, r1, r2, r3);
                bfl[2*g][0] = r0; bfl[2*g][1] = r2;
                bfl[2*g+1][0] = r1; bfl[2*g+1][1] = r3;
            }
            u32 af[4][4];
            #pragma unroll
            for (int mi = 0; mi < 4; mi++) {
                int ra = wm + mi * 16 + (lane & 15);
                u32 off = (u32)(ra * 128 + ((cidx ^ (ra & 7)) << 4));
                ldsm4(sAh + off, af[mi][0], af[mi][1], af[mi][2], af[mi][3]);
            }
            #pragma unroll
            for (int mi = 0; mi < 4; mi++)
                #pragma unroll
                for (int nj = 0; nj < 4; nj++)
                    mma_bf16(acc[mi][nj], af[mi], bfh[nj]);
            #pragma unroll
            for (int mi = 0; mi < 4; mi++)
                #pragma unroll
                for (int nj = 0; nj < 4; nj++)
                    mma_bf16(acc[mi][nj], af[mi], bfl[nj]);
            #pragma unroll
            for (int mi = 0; mi < 4; mi++) {
                int ra = wm + mi * 16 + (lane & 15);
                u32 off = (u32)(ra * 128 + ((cidx ^ (ra & 7)) << 4));
                ldsm4(sAl + off, af[mi][0], af[mi][1], af[mi][2], af[mi][3]);
            }
            #pragma unroll
            for (int mi = 0; mi < 4; mi++)
                #pragma unroll
                for (int nj = 0; nj < 4; nj++)
                    mma_bf16(acc[mi][nj], af[mi], bfh[nj]);
        }
    }

    const int lr = lane >> 2;
    const int lc = (lane & 3) * 2;
    #pragma unroll
    for (int mi = 0; mi < 4; mi++) {
        #pragma unroll
        for (int half = 0; half < 2; half++) {
            int r = m0 + wm + mi * 16 + lr + half * 8;
            #pragma unroll
            for (int nj = 0; nj < 4; nj++) {
                int col = n0 + wn + nj * 8 + lc;
                float2 bv = *(const float2*)(bias + col);
                float v0 = (acc[mi][nj][half * 2]     + bv.x) * scale;
                float v1 = (acc[mi][nj][half * 2 + 1] + bv.y) * scale;
                if (mode == 0) {
                    size_t o = (size_t)r * N + col;
                    if (res) {
                        float2 rv = *(const float2*)(res + o);
                        v0 += rv.x; v1 += rv.y;
                    }
                    *(float2*)(outf + o) = make_float2(v0, v1);
                } else if (mode == 2) {
                    size_t o = (size_t)r * N + col;
                    u32 hi, lo;
                    splitpack(v0, v1, hi, lo);
                    *(u32*)(outh + o) = hi;
                    *(u32*)(outl + o) = lo;
                } else { // mode 3: head-layout fp16 split
                    int b_ = r >> 11, l = r & 2047;
                    int h  = col >> 6, d = col & 63;
                    size_t o = (((size_t)(b_ * HH + h)) * LL + l) * DDIM + d;
                    u32 hi, lo;
                    splitpack_h(v0, v1, hi, lo);
                    *(u32*)(outfh + o) = hi;
                    *(u32*)(outfl + o) = lo;
                }
            }
        }
    }
}

// ===================== flash attention (fp16 2-pass mma) =====================
// grid (16, 32, 2), 256 thr, 2 CTAs/SM. 128 q-rows/block, K-tiles of 64.
// S = Qh*(Kh+Kl); O = Ph*(Vh+Vl). P stays in registers.
#define FK_SMEM (48*1024 + 128)

__global__ __launch_bounds__(256, 2) void flash_mma(
    const f16* __restrict__ qk0h, const f16* __restrict__ qk0l,
    const f16* __restrict__ qk1h, const f16* __restrict__ qk1l,
    const f16* __restrict__ v0h,  const f16* __restrict__ v0l,
    const f16* __restrict__ v1h,  const f16* __restrict__ v1l,
    bf16* __restrict__ m0h, bf16* __restrict__ m0l,
    bf16* __restrict__ m1h, bf16* __restrict__ m1l)
{
    extern __shared__ char dsm[];
    u32 sb0 = smem_u32(dsm);
    u32 sb  = (sb0 + 127) & ~127u;
    char* smp = dsm + (sb - sb0);

    const int dir = blockIdx.z;
    const f16* qh = dir ? qk1h : qk0h;
    const f16* kh = dir ? qk0h : qk1h;
    const f16* kl = dir ? qk0l : qk1l;
    const f16* vh = dir ? v0h : v1h;
    const f16* vl = dir ? v0l : v1l;
    bf16* ohp = dir ? m1h : m0h;
    bf16* olp = dir ? m1l : m0l;

    const int bh = blockIdx.y;
    const size_t base = (size_t)bh * LL * DDIM;
    const int q0 = blockIdx.x * 128;
    const int tid  = threadIdx.x;
    const int wid  = tid >> 5;
    const int lane = tid & 31;
    const int g  = lane >> 2;
    const int t4 = lane & 3;
    const int rb = lane & 15;
    const int chsel = lane >> 4;

    const u32 sQ  = sb;            // 128 x 64 f16 = 16KB
    const u32 sKh = sb + 16384;    // 64 x 64 f16 = 8KB
    const u32 sKl = sb + 24576;
    const u32 sVh = sb + 32768;
    const u32 sVl = sb + 40960;

    // load Q-hi tile (128x64), swizzled rows of 128B
    #pragma unroll
    for (int rep = 0; rep < 2; rep++) {
        int idx = rep * 256 + tid;
        int row = idx >> 2, ch2 = idx & 3;     // 2 uint4 per thread-slot
        #pragma unroll
        for (int s = 0; s < 2; s++) {
            int ch = ch2 * 2 + s;
            u32 soff = (u32)(row * 128 + ((ch ^ (row & 7)) << 4));
            *(uint4*)(smp + soff) =
                *(const uint4*)(qh + base + (size_t)(q0 + row) * DDIM + ch * 8);
        }
    }
    __syncthreads();

    // Q fragments (per warp 16 rows, 4 k16 steps, hi only)
    u32 qf[4][4];
    {
        int qr = wid * 16 + rb;
        #pragma unroll
        for (int ks = 0; ks < 4; ks++) {
            int chunk = ks * 2 + chsel;
            u32 off = (u32)(qr * 128 + ((chunk ^ (qr & 7)) << 4));
            ldsm4(sQ + off, qf[ks][0], qf[ks][1], qf[ks][2], qf[ks][3]);
        }
    }

    float mrow0 = -1e30f, mrow1 = -1e30f, lrow0 = 0.f, lrow1 = 0.f;
    float oacc[8][4];
    #pragma unroll
    for (int dt = 0; dt < 8; dt++)
        #pragma unroll
        for (int t = 0; t < 4; t++) oacc[dt][t] = 0.f;

    for (int it = 0; it < 32; it++) {
        __syncthreads();
        const int k0 = it * 64;
        // load K/V tiles (64 rows x 64 f16, hi+lo): 4 buffers x 512 u4 / 256thr
        {
            int row = tid >> 2;            // 0..63
            int ch2 = tid & 3;
            #pragma unroll
            for (int s = 0; s < 2; s++) {
                int ch = ch2 * 2 + s;
                u32 soff = (u32)(row * 128 + ((ch ^ (row & 7)) << 4));
                size_t goff = base + (size_t)(k0 + row) * DDIM + ch * 8;
                *(uint4*)(smp + 16384 + soff) = *(const uint4*)(kh + goff);
                *(uint4*)(smp + 24576 + soff) = *(const uint4*)(kl + goff);
                *(uint4*)(smp + 32768 + soff) = *(const uint4*)(vh + goff);
                *(uint4*)(smp + 40960 + soff) = *(const uint4*)(vl + goff);
            }
        }
        __syncthreads();

        // ---- S = Qh (Kh + Kl)^T ----
        float acc[8][4];
        #pragma unroll
        for (int nt = 0; nt < 8; nt++)
            #pragma unroll
            for (int t = 0; t < 4; t++) acc[nt][t] = 0.f;

        #pragma unroll
        for (int ks = 0; ks < 4; ks++) {
            int chunk = ks * 2 + chsel;
            #pragma unroll
            for (int gg = 0; gg < 4; gg++) {
                int rr = gg * 16 + rb;
                u32 off = (u32)(rr * 128 + ((chunk ^ (rr & 7)) << 4));
                u32 r0, r1, r2, r3;
                ldsm4(sKh + off, r0, r1, r2, r3);
                { u32 bfa[2] = {r0, r2}; mma_f16(acc[2*gg],   qf[ks], bfa); }
                { u32 bfb[2] = {r1, r3}; mma_f16(acc[2*gg+1], qf[ks], bfb); }
                ldsm4(sKl + off, r0, r1, r2, r3);
                { u32 bfa[2] = {r0, r2}; mma_f16(acc[2*gg],   qf[ks], bfa); }
                { u32 bfb[2] = {r1, r3}; mma_f16(acc[2*gg+1], qf[ks], bfb); }
            }
        }

        // ---- online softmax (rows g and g+8) ----
        float mx0 = -1e30f, mx1 = -1e30f;
        #pragma unroll
        for (int nt = 0; nt < 8; nt++) {
            mx0 = fmaxf(mx0, fmaxf(acc[nt][0], acc[nt][1]));
            mx1 = fmaxf(mx1, fmaxf(acc[nt][2], acc[nt][3]));
        }
        mx0 = fmaxf(mx0, __shfl_xor_sync(0xffffffffu, mx0, 1));
        mx0 = fmaxf(mx0, __shfl_xor_sync(0xffffffffu, mx0, 2));
        mx1 = fmaxf(mx1, __shfl_xor_sync(0xffffffffu, mx1, 1));
        mx1 = fmaxf(mx1, __shfl_xor_sync(0xffffffffu, mx1, 2));
        float mn0 = fmaxf(mrow0, mx0), mn1 = fmaxf(mrow1, mx1);
        float al0 = __expf(mrow0 - mn0), al1 = __expf(mrow1 - mn1);
        mrow0 = mn0; mrow1 = mn1;
        float s0 = 0.f, s1 = 0.f;
        #pragma unroll
        for (int nt = 0; nt < 8; nt++) {
            acc[nt][0] = __expf(acc[nt][0] - mn0);
            acc[nt][1] = __expf(acc[nt][1] - mn0);
            acc[nt][2] = __expf(acc[nt][2] - mn1);
            acc[nt][3] = __expf(acc[nt][3] - mn1);
            s0 += acc[nt][0] + acc[nt][1];
            s1 += acc[nt][2] + acc[nt][3];
        }
        s0 += __shfl_xor_sync(0xffffffffu, s0, 1);
        s0 += __shfl_xor_sync(0xffffffffu, s0, 2);
        s1 += __shfl_xor_sync(0xffffffffu, s1, 1);
        s1 += __shfl_xor_sync(0xffffffffu, s1, 2);
        lrow0 = lrow0 * al0 + s0;
        lrow1 = lrow1 * al1 + s1;
        #pragma unroll
        for (int dt = 0; dt < 8; dt++) {
            oacc[dt][0] *= al0; oacc[dt][1] *= al0;
            oacc[dt][2] *= al1; oacc[dt][3] *= al1;
        }

        // ---- pack P-hi (C-frag -> A-frag) ----
        u32 ph[4][4];
        #pragma unroll
        for (int kb = 0; kb < 4; kb++) {
            ph[kb][0] = pack_h2(acc[2*kb][0],   acc[2*kb][1]);
            ph[kb][1] = pack_h2(acc[2*kb][2],   acc[2*kb][3]);
            ph[kb][2] = pack_h2(acc[2*kb+1][0], acc[2*kb+1][1]);
            ph[kb][3] = pack_h2(acc[2*kb+1][2], acc[2*kb+1][3]);
        }

        // ---- O += Ph (Vh + Vl) ----
        #pragma unroll
        for (int kb = 0; kb < 4; kb++) {
            int rr = kb * 16 + rb;
            #pragma unroll
            for (int dg = 0; dg < 4; dg++) {
                int chunk = dg * 2 + chsel;
                u32 off = (u32)(rr * 128 + ((chunk ^ (rr & 7)) << 4));
                u32 r0, r1, r2, r3;
                ldsm4t(sVh + off, r0, r1, r2, r3);
                { u32 vfa[2] = {r0, r1}; mma_f16(oacc[2*dg],   ph[kb], vfa); }
                { u32 vfb[2] = {r2, r3}; mma_f16(oacc[2*dg+1], ph[kb], vfb); }
                ldsm4t(sVl + off, r0, r1, r2, r3);
                { u32 vfa[2] = {r0, r1}; mma_f16(oacc[2*dg],   ph[kb], vfa); }
                { u32 vfb[2] = {r2, r3}; mma_f16(oacc[2*dg+1], ph[kb], vfb); }
            }
        }
    }

    // ---- epilogue: normalize, split-store merged (B,L,C) ----
    float inv0 = 1.f / lrow0, inv1 = 1.f / lrow1;
    int r0g = q0 + wid * 16 + g;
    int bb = bh >> 2, hh = bh & 3;
    #pragma unroll
    for (int dt = 0; dt < 8; dt++) {
        int col = hh * DDIM + dt * 8 + t4 * 2;
        size_t o0 = (size_t)(bb * LL + r0g) * CC + col;
        size_t o1 = (size_t)(bb * LL + r0g + 8) * CC + col;
        u32 hi, lo;
        splitpack(oacc[dt][0] * inv0, oacc[dt][1] * inv0, hi, lo);
        *(u32*)(ohp + o0) = hi; *(u32*)(olp + o0) = lo;
        splitpack(oacc[dt][2] * inv1, oacc[dt][3] * inv1, hi, lo);
        *(u32*)(ohp + o1) = hi; *(u32*)(olp + o1) = lo;
    }
}

// ===================== LayerNorm + exact GELU -> split bf16 =====================
__global__ __launch_bounds__(256) void ln_gelu_kernel(
    const float* __restrict__ h0, const float* __restrict__ h1,
    bf16* __restrict__ h0h, bf16* __restrict__ h0l,
    bf16* __restrict__ h1h, bf16* __restrict__ h1l,
    const float* __restrict__ g, const float* __restrict__ bta)
{
    const float* hp = blockIdx.y ? h1 : h0;
    bf16* oh = blockIdx.y ? h1h : h0h;
    bf16* olo = blockIdx.y ? h1l : h0l;
    const size_t rowoff = (size_t)blockIdx.x * C2;
    const int tid = threadIdx.x;
    const int lane = tid & 31, wid = tid >> 5;

    float2 v = *(const float2*)&hp[rowoff + tid * 2];
    float s  = v.x + v.y;
    float sq = v.x * v.x + v.y * v.y;
    #pragma unroll
    for (int off = 16; off; off >>= 1) {
        s  += __shfl_xor_sync(0xffffffffu, s,  off);
        sq += __shfl_xor_sync(0xffffffffu, sq, off);
    }
    __shared__ float rs[8], rq[8];
    if (lane == 0) { rs[wid] = s; rq[wid] = sq; }
    __syncthreads();
    if (wid == 0) {
        s  = (lane < 8) ? rs[lane] : 0.f;
        sq = (lane < 8) ? rq[lane] : 0.f;
        #pragma unroll
        for (int off = 4; off; off >>= 1) {
            s  += __shfl_xor_sync(0xffffffffu, s,  off);
            sq += __shfl_xor_sync(0xffffffffu, sq, off);
        }
        if (lane == 0) { rs[0] = s; rq[0] = sq; }
    }
    __syncthreads();
    float mean = rs[0] * (1.f / 512.f);
    float var  = rq[0] * (1.f / 512.f) - mean * mean;
    float rstd = rsqrtf(var + 1e-5f);

    int c0 = tid * 2;
    float x0n = (v.x - mean) * rstd * g[c0]     + bta[c0];
    float x1n = (v.y - mean) * rstd * g[c0 + 1] + bta[c0 + 1];
    x0n = 0.5f * x0n * (1.f + erff(x0n * 0.70710678118654752f));
    x1n = 0.5f * x1n * (1.f + erff(x1n * 0.70710678118654752f));

    u32 hi, lo;
    splitpack(x0n, x1n, hi, lo);
    *(u32*)(oh + rowoff + c0)  = hi;
    *(u32*)(olo + rowoff + c0) = lo;
}

// ===================== launch =====================
extern "C" void kernel_launch(void* const* d_in, const int* in_sizes, int n_in,
                              void* d_out, int out_size)
{
    const float* x0   = (const float*)d_in[0];
    const float* x1   = (const float*)d_in[1];
    const float* Wqk  = (const float*)d_in[2];
    const float* bqk  = (const float*)d_in[3];
    const float* Wv   = (const float*)d_in[4];
    const float* bv   = (const float*)d_in[5];
    const float* Wout = (const float*)d_in[6];
    const float* bout = (const float*)d_in[7];
    const float* W1   = (const float*)d_in[8];
    const float* b1   = (const float*)d_in[9];
    const float* ln_g = (const float*)d_in[10];
    const float* ln_b = (const float*)d_in[11];
    const float* W2   = (const float*)d_in[12];
    const float* b2   = (const float*)d_in[13];
    float* out = (float*)d_out;

    float *p_h0, *p_h1;
    bf16 *px0h, *px0l, *px1h, *px1l;
    bf16 *pm0h, *pm0l, *pm1h, *pm1l;
    bf16 *pp0h, *pp0l, *pp1h, *pp1l;
    bf16 *ph0h, *ph0l, *ph1h, *ph1l;
    f16 *pq0h, *pq0l, *pq1h, *pq1l, *pv0h, *pv0l, *pv1h, *pv1l;
    bf16 *pWqkh, *pWqkl, *pWvh, *pWvl, *pWoth, *pWotl, *pW1h, *pW1l, *pW2h, *pW2l;

    cudaGetSymbolAddress((void**)&p_h0,  g_h0);
    cudaGetSymbolAddress((void**)&p_h1,  g_h1);
    cudaGetSymbolAddress((void**)&px0h, g_x0h); cudaGetSymbolAddress((void**)&px0l, g_x0l);
    cudaGetSymbolAddress((void**)&px1h, g_x1h); cudaGetSymbolAddress((void**)&px1l, g_x1l);
    cudaGetSymbolAddress((void**)&pm0h, g_m0h); cudaGetSymbolAddress((void**)&pm0l, g_m0l);
    cudaGetSymbolAddress((void**)&pm1h, g_m1h); cudaGetSymbolAddress((void**)&pm1l, g_m1l);
    cudaGetSymbolAddress((void**)&pp0h, g_p0h); cudaGetSymbolAddress((void**)&pp0l, g_p0l);
    cudaGetSymbolAddress((void**)&pp1h, g_p1h); cudaGetSymbolAddress((void**)&pp1l, g_p1l);
    cudaGetSymbolAddress((void**)&ph0h, g_h0h); cudaGetSymbolAddress((void**)&ph0l, g_h0l);
    cudaGetSymbolAddress((void**)&ph1h, g_h1h); cudaGetSymbolAddress((void**)&ph1l, g_h1l);
    cudaGetSymbolAddress((void**)&pq0h, g_qk0h); cudaGetSymbolAddress((void**)&pq0l, g_qk0l);
    cudaGetSymbolAddress((void**)&pq1h, g_qk1h); cudaGetSymbolAddress((void**)&pq1l, g_qk1l);
    cudaGetSymbolAddress((void**)&pv0h, g_v0h);  cudaGetSymbolAddress((void**)&pv0l, g_v0l);
    cudaGetSymbolAddress((void**)&pv1h, g_v1h);  cudaGetSymbolAddress((void**)&pv1l, g_v1l);
    cudaGetSymbolAddress((void**)&pWqkh, g_Wqkh); cudaGetSymbolAddress((void**)&pWqkl, g_Wqkl);
    cudaGetSymbolAddress((void**)&pWvh,  g_Wvh);  cudaGetSymbolAddress((void**)&pWvl,  g_Wvl);
    cudaGetSymbolAddress((void**)&pWoth, g_Woth); cudaGetSymbolAddress((void**)&pWotl, g_Wotl);
    cudaGetSymbolAddress((void**)&pW1h,  g_W1h);  cudaGetSymbolAddress((void**)&pW1l,  g_W1l);
    cudaGetSymbolAddress((void**)&pW2h,  g_W2h);  cudaGetSymbolAddress((void**)&pW2l,  g_W2l);

    cudaFuncSetAttribute(mma_gemm,
                         cudaFuncAttributeMaxDynamicSharedMemorySize, MG_SMEM);
    cudaFuncSetAttribute(flash_mma,
                         cudaFuncAttributeMaxDynamicSharedMemorySize, FK_SMEM);

    const float qscale = 0.35355339059327373f; // 64^-0.25

    split_kernel<<<RR * CC / 1024, 256>>>(x0, px0h, px0l, RR * CC);
    split_kernel<<<RR * CC / 1024, 256>>>(x1, px1h, px1l, RR * CC);
    wsplit_kernel<<<dim3(CC/32, CC/32), dim3(32,8)>>>(Wqk,  pWqkh, pWqkl, CC, CC);
    wsplit_kernel<<<dim3(CC/32, CC/32), dim3(32,8)>>>(Wv,   pWvh,  pWvl,  CC, CC);
    wsplit_kernel<<<dim3(CC/32, CC/32), dim3(32,8)>>>(Wout, pWoth, pWotl, CC, CC);
    wsplit_kernel<<<dim3(C2/32, C2/32), dim3(32,8)>>>(W1,   pW1h,  pW1l,  C2, C2);
    wsplit_kernel<<<dim3(CC/32, C2/32), dim3(32,8)>>>(W2,   pW2h,  pW2l,  C2, CC);

    dim3 g256(2, 128);
    dim3 g512(4, 128);

    // QK / V projections -> fp16 split head layout (mode 3)
    mma_gemm<<<g256, 256, MG_SMEM>>>(px0h, px0l, CC, nullptr, nullptr, 0,
        pWqkh, pWqkl, bqk, nullptr, nullptr, nullptr, nullptr, pq0h, pq0l, CC, qscale, 3);
    mma_gemm<<<g256, 256, MG_SMEM>>>(px1h, px1l, CC, nullptr, nullptr, 0,
        pWqkh, pWqkl, bqk, nullptr, nullptr, nullptr, nullptr, pq1h, pq1l, CC, qscale, 3);
    mma_gemm<<<g256, 256, MG_SMEM>>>(px0h, px0l, CC, nullptr, nullptr, 0,
        pWvh, pWvl, bv, nullptr, nullptr, nullptr, nullptr, pv0h, pv0l, CC, 1.f, 3);
    mma_gemm<<<g256, 256, MG_SMEM>>>(px1h, px1l, CC, nullptr, nullptr, 0,
        pWvh, pWvl, bv, nullptr, nullptr, nullptr, nullptr, pv1h, pv1l, CC, 1.f, 3);

    // dual flash attention (fp16 tensor-core) -> split bf16 merged
    dim3 fg(LL / 128, BB * HH, 2);
    flash_mma<<<fg, 256, FK_SMEM>>>(pq0h, pq0l, pq1h, pq1l,
                                    pv0h, pv0l, pv1h, pv1l,
                                    pm0h, pm0l, pm1h, pm1l);

    // output projection -> split bf16
    mma_gemm<<<g256, 256, MG_SMEM>>>(pm0h, pm0l, CC, nullptr, nullptr, 0,
        pWoth, pWotl, bout, nullptr, nullptr, pp0h, pp0l, nullptr, nullptr, CC, 1.f, 2);
    mma_gemm<<<g256, 256, MG_SMEM>>>(pm1h, pm1l, CC, nullptr, nullptr, 0,
        pWoth, pWotl, bout, nullptr, nullptr, pp1h, pp1l, nullptr, nullptr, CC, 1.f, 2);

    // FFN-1 on virtual concat([x, p]) -> f32
    mma_gemm<<<g512, 256, MG_SMEM>>>(px0h, px0l, CC, pp0h, pp0l, CC,
        pW1h, pW1l, b1, nullptr, p_h0, nullptr, nullptr, nullptr, nullptr, C2, 1.f, 0);
    mma_gemm<<<g512, 256, MG_SMEM>>>(px1h, px1l, CC, pp1h, pp1l, CC,
        pW1h, pW1l, b1, nullptr, p_h1, nullptr, nullptr, nullptr, nullptr, C2, 1.f, 0);

    // LayerNorm + GELU -> split bf16
    dim3 lg(RR, 2);
    ln_gelu_kernel<<<lg, 256>>>(p_h0, p_h1, ph0h, ph0l, ph1h, ph1l, ln_g, ln_b);

    // FFN-2 + residual -> outputs
    mma_gemm<<<g256, 256, MG_SMEM>>>(ph0h, ph0l, C2, nullptr, nullptr, 0,
        pW2h, pW2l, b2, x0, out, nullptr, nullptr, nullptr, nullptr, CC, 1.f, 0);
    mma_gemm<<<g256, 256, MG_SMEM>>>(ph1h, ph1l, C2, nullptr, nullptr, 0,
        pW2h, pW2l, b2, x1, out + (size_t)RR * CC, nullptr, nullptr, nullptr, nullptr, CC, 1.f, 0);
}

// round 8
// speedup vs baseline: 2.6302x; 1.2464x over previous
#include <cuda_runtime.h>
#include <cuda_bf16.h>
#include <cuda_fp16.h>
#include <math.h>
#include <stdint.h>

#define BB 8
#define LL 2048
#define CC 256
#define HH 4
#define DDIM 64
#define RR (BB*LL)
#define C2 (2*CC)

typedef unsigned long long u64;
typedef unsigned int u32;
typedef __nv_bfloat16 bf16;
typedef __half f16;

__device__ __forceinline__ void split1(float x, bf16& h_, bf16& l_) {
    h_ = __float2bfloat16(x);
    l_ = __float2bfloat16(x - __bfloat162float(h_));
}
__device__ __forceinline__ void splitpack(float a, float b, u32& hi, u32& lo) {
    bf16 ah, al, bh_, bl_;
    split1(a, ah, al); split1(b, bh_, bl_);
    __nv_bfloat162 th, tl;
    th.x = ah; th.y = bh_; tl.x = al; tl.y = bl_;
    hi = *(u32*)&th; lo = *(u32*)&tl;
}
__device__ __forceinline__ u32 pack_h2(float a, float b) {
    __half2 t = __halves2half2(__float2half_rn(a), __float2half_rn(b));
    return *(u32*)&t;
}
__device__ __forceinline__ u32 smem_u32(const void* p) {
    u32 a;
    asm("{ .reg .u64 t; cvta.to.shared.u64 t, %1; cvt.u32.u64 %0, t; }"
        : "=r"(a) : "l"(p));
    return a;
}
__device__ __forceinline__ void ldsm4(u32 addr, u32& r0, u32& r1, u32& r2, u32& r3) {
    asm volatile("ldmatrix.sync.aligned.m8n8.x4.shared.b16 {%0,%1,%2,%3}, [%4];"
                 : "=r"(r0), "=r"(r1), "=r"(r2), "=r"(r3) : "r"(addr));
}
__device__ __forceinline__ void ldsm4t(u32 addr, u32& r0, u32& r1, u32& r2, u32& r3) {
    asm volatile("ldmatrix.sync.aligned.m8n8.x4.trans.shared.b16 {%0,%1,%2,%3}, [%4];"
                 : "=r"(r0), "=r"(r1), "=r"(r2), "=r"(r3) : "r"(addr));
}
__device__ __forceinline__ void mma_bf16(float* c, const u32* a, const u32* b) {
    asm volatile(
        "mma.sync.aligned.m16n8k16.row.col.f32.bf16.bf16.f32 "
        "{%0,%1,%2,%3},{%4,%5,%6,%7},{%8,%9},{%0,%1,%2,%3};"
        : "+f"(c[0]), "+f"(c[1]), "+f"(c[2]), "+f"(c[3])
        : "r"(a[0]), "r"(a[1]), "r"(a[2]), "r"(a[3]), "r"(b[0]), "r"(b[1]));
}
__device__ __forceinline__ void mma_f16(float* c, const u32* a, const u32* b) {
    asm volatile(
        "mma.sync.aligned.m16n8k16.row.col.f32.f16.f16.f32 "
        "{%0,%1,%2,%3},{%4,%5,%6,%7},{%8,%9},{%0,%1,%2,%3};"
        : "+f"(c[0]), "+f"(c[1]), "+f"(c[2]), "+f"(c[3])
        : "r"(a[0]), "r"(a[1]), "r"(a[2]), "r"(a[3]), "r"(b[0]), "r"(b[1]));
}
#define CP_ASYNC16(smem, gptr) \
    asm volatile("cp.async.cg.shared.global [%0], [%1], 16;" \
                 :: "r"(smem), "l"(gptr) : "memory")
#define CP_COMMIT() asm volatile("cp.async.commit_group;" ::: "memory")
#define CP_WAIT1()  asm volatile("cp.async.wait_group 1;" ::: "memory")
#define CP_WAIT0()  asm volatile("cp.async.wait_group 0;" ::: "memory")

// ===================== scratch =====================
__device__ float g_h0 [RR*C2];
__device__ float g_h1 [RR*C2];

__device__ bf16 g_x0h[RR*CC], g_x0l[RR*CC], g_x1h[RR*CC], g_x1l[RR*CC];
__device__ bf16 g_m0h[RR*CC], g_m0l[RR*CC], g_m1h[RR*CC], g_m1l[RR*CC];
__device__ bf16 g_p0h[RR*CC], g_p0l[RR*CC], g_p1h[RR*CC], g_p1l[RR*CC];
__device__ bf16 g_h0h[RR*C2], g_h0l[RR*C2], g_h1h[RR*C2], g_h1l[RR*C2];

__device__ f16 g_qk0[BB*HH*LL*DDIM];
__device__ f16 g_qk1[BB*HH*LL*DDIM];
__device__ f16 g_v0 [BB*HH*LL*DDIM];
__device__ f16 g_v1 [BB*HH*LL*DDIM];

__device__ bf16 g_Wqkh[CC*CC], g_Wqkl[CC*CC];
__device__ bf16 g_Wvh [CC*CC], g_Wvl [CC*CC];
__device__ bf16 g_Woth[CC*CC], g_Wotl[CC*CC];
__device__ bf16 g_W1h [C2*C2], g_W1l [C2*C2];
__device__ bf16 g_W2h [CC*C2], g_W2l [CC*C2];

// ===================== split f32 -> bf16 hi/lo =====================
__global__ __launch_bounds__(256) void split_kernel(
    const float* __restrict__ x, bf16* __restrict__ hi, bf16* __restrict__ lo, int n)
{
    int i = (blockIdx.x * 256 + threadIdx.x) * 4;
    if (i >= n) return;
    float4 v = *(const float4*)(x + i);
    uint2 uh, ul;
    splitpack(v.x, v.y, uh.x, ul.x);
    splitpack(v.z, v.w, uh.y, ul.y);
    *(uint2*)(hi + i) = uh;
    *(uint2*)(lo + i) = ul;
}

// ===================== transpose W [K,N] -> split [N,K] =====================
__global__ __launch_bounds__(256) void wsplit_kernel(
    const float* __restrict__ W, bf16* __restrict__ hi, bf16* __restrict__ lo,
    int K, int N)
{
    __shared__ float t[32][33];
    int nb = blockIdx.x * 32, kb = blockIdx.y * 32;
    int tx = threadIdx.x, ty0 = threadIdx.y;
    #pragma unroll
    for (int r = 0; r < 4; r++) {
        int ty = ty0 + r * 8;
        t[ty][tx] = W[(size_t)(kb + ty) * N + nb + tx];
    }
    __syncthreads();
    #pragma unroll
    for (int r = 0; r < 4; r++) {
        int ty = ty0 + r * 8;
        float v = t[tx][ty];
        bf16 h_, l_;
        split1(v, h_, l_);
        size_t o = (size_t)(nb + ty) * K + kb + tx;
        hi[o] = h_; lo[o] = l_;
    }
}

// ===================== mma.sync split-bf16 GEMM =====================
// mode: 0 = f32 out (+res), 2 = split bf16 out, 3 = fp16 head-layout
#define MG_SMEM (64*1024 + 128)

__global__ __launch_bounds__(256, 2) void mma_gemm(
    const bf16* __restrict__ a0h, const bf16* __restrict__ a0l, int K0,
    const bf16* __restrict__ a1h, const bf16* __restrict__ a1l, int K1,
    const bf16* __restrict__ bh, const bf16* __restrict__ bl,
    const float* __restrict__ bias,
    const float* __restrict__ res,
    float* __restrict__ outf,
    bf16* __restrict__ outh, bf16* __restrict__ outl,
    f16* __restrict__ outfh,
    int N, float scale, int mode)
{
    extern __shared__ char dsm[];
    u32 sb0 = smem_u32(dsm);
    u32 sb  = (sb0 + 127) & ~127u;
    char* smp = dsm + (sb - sb0);

    const int tid  = threadIdx.x;
    const int wid  = tid >> 5;
    const int lane = tid & 31;

    const int m0 = blockIdx.y * 128;
    const int n0 = blockIdx.x * 128;
    const int KB = K0 + K1;
    const int nc0 = K0 >> 6;
    const int nc  = KB >> 6;

    const int wm = (wid >> 2) * 64;
    const int wn = (wid & 3) * 32;

    const u32 sAh = sb;
    const u32 sAl = sb + 16384;
    const u32 sBh = sb + 32768;
    const u32 sBl = sb + 49152;

    float acc[4][4][4];
    #pragma unroll
    for (int i = 0; i < 4; i++)
        #pragma unroll
        for (int j = 0; j < 4; j++)
            #pragma unroll
            for (int t = 0; t < 4; t++) acc[i][j][t] = 0.f;

    const int ld_row = tid >> 3;
    const int ld_ch  = tid & 7;

    for (int c = 0; c < nc; c++) {
        __syncthreads();
        const bf16 *Ah, *Al;
        int astr, koff;
        if (c < nc0) { Ah = a0h; Al = a0l; astr = K0; koff = c << 6; }
        else         { Ah = a1h; Al = a1l; astr = K1; koff = (c - nc0) << 6; }
        const int koffB = c << 6;

        #pragma unroll
        for (int i = 0; i < 4; i++) {
            int row = ld_row + i * 32;
            u32 off = (u32)(row * 128 + ((ld_ch ^ (row & 7)) << 4));
            *(uint4*)(smp + off) =
                *(const uint4*)(Ah + (size_t)(m0 + row) * astr + koff + ld_ch * 8);
            *(uint4*)(smp + 16384 + off) =
                *(const uint4*)(Al + (size_t)(m0 + row) * astr + koff + ld_ch * 8);
            *(uint4*)(smp + 32768 + off) =
                *(const uint4*)(bh + (size_t)(n0 + row) * KB + koffB + ld_ch * 8);
            *(uint4*)(smp + 49152 + off) =
                *(const uint4*)(bl + (size_t)(n0 + row) * KB + koffB + ld_ch * 8);
        }
        __syncthreads();

        #pragma unroll
        for (int ks = 0; ks < 4; ks++) {
            const int cidx = ks * 2 + (lane >> 4);
            u32 bfh[4][2], bfl[4][2];
            #pragma unroll
            for (int g = 0; g < 2; g++) {
                int rb = wn + g * 16 + (lane & 15);
                u32 off = (u32)(rb * 128 + ((cidx ^ (rb & 7)) << 4));
                u32 r0, r1, r2, r3;
                ldsm4(sBh + off, r0, r1, r2, r3);
                bfh[2*g][0] = r0; bfh[2*g][1] = r2;
                bfh[2*g+1][0] = r1; bfh[2*g+1][1] = r3;
                ldsm4(sBl + off, r0, r1, r2, r3);
                bfl[2*g][0] = r0; bfl[2*g][1] = r2;
                bfl[2*g+1][0] = r1; bfl[2*g+1][1] = r3;
            }
            u32 af[4][4];
            #pragma unroll
            for (int mi = 0; mi < 4; mi++) {
                int ra = wm + mi * 16 + (lane & 15);
                u32 off = (u32)(ra * 128 + ((cidx ^ (ra & 7)) << 4));
                ldsm4(sAh + off, af[mi][0], af[mi][1], af[mi][2], af[mi][3]);
            }
            #pragma unroll
            for (int mi = 0; mi < 4; mi++)
                #pragma unroll
                for (int nj = 0; nj < 4; nj++)
                    mma_bf16(acc[mi][nj], af[mi], bfh[nj]);
            #pragma unroll
            for (int mi = 0; mi < 4; mi++)
                #pragma unroll
                for (int nj = 0; nj < 4; nj++)
                    mma_bf16(acc[mi][nj], af[mi], bfl[nj]);
            #pragma unroll
            for (int mi = 0; mi < 4; mi++) {
                int ra = wm + mi * 16 + (lane & 15);
                u32 off = (u32)(ra * 128 + ((cidx ^ (ra & 7)) << 4));
                ldsm4(sAl + off, af[mi][0], af[mi][1], af[mi][2], af[mi][3]);
            }
            #pragma unroll
            for (int mi = 0; mi < 4; mi++)
                #pragma unroll
                for (int nj = 0; nj < 4; nj++)
                    mma_bf16(acc[mi][nj], af[mi], bfh[nj]);
        }
    }

    const int lr = lane >> 2;
    const int lc = (lane & 3) * 2;
    #pragma unroll
    for (int mi = 0; mi < 4; mi++) {
        #pragma unroll
        for (int half = 0; half < 2; half++) {
            int r = m0 + wm + mi * 16 + lr + half * 8;
            #pragma unroll
            for (int nj = 0; nj < 4; nj++) {
                int col = n0 + wn + nj * 8 + lc;
                float2 bv = *(const float2*)(bias + col);
                float v0 = (acc[mi][nj][half * 2]     + bv.x) * scale;
                float v1 = (acc[mi][nj][half * 2 + 1] + bv.y) * scale;
                if (mode == 0) {
                    size_t o = (size_t)r * N + col;
                    if (res) {
                        float2 rv = *(const float2*)(res + o);
                        v0 += rv.x; v1 += rv.y;
                    }
                    *(float2*)(outf + o) = make_float2(v0, v1);
                } else if (mode == 2) {
                    size_t o = (size_t)r * N + col;
                    u32 hi, lo;
                    splitpack(v0, v1, hi, lo);
                    *(u32*)(outh + o) = hi;
                    *(u32*)(outl + o) = lo;
                } else { // mode 3: head-layout fp16
                    int b_ = r >> 11, l = r & 2047;
                    int h  = col >> 6, d = col & 63;
                    size_t o = (((size_t)(b_ * HH + h)) * LL + l) * DDIM + d;
                    *(u32*)(outfh + o) = pack_h2(v0, v1);
                }
            }
        }
    }
}

// ===================== flash attention (fp16 single-pass, cp.async pipeline) =====================
// grid (16, 32, 2), 256 thr, 2 CTAs/SM. 128 q-rows/block, K-tiles of 64, 2-stage pipeline.
#define FK_SMEM (48*1024 + 128)

__global__ __launch_bounds__(256, 2) void flash_mma(
    const f16* __restrict__ qk0, const f16* __restrict__ qk1,
    const f16* __restrict__ v0,  const f16* __restrict__ v1,
    bf16* __restrict__ m0h, bf16* __restrict__ m0l,
    bf16* __restrict__ m1h, bf16* __restrict__ m1l)
{
    extern __shared__ char dsm[];
    u32 sb0 = smem_u32(dsm);
    u32 sb  = (sb0 + 127) & ~127u;
    char* smp = dsm + (sb - sb0);

    const int dir = blockIdx.z;
    const f16* qh = dir ? qk1 : qk0;
    const f16* kh = dir ? qk0 : qk1;
    const f16* vh = dir ? v0 : v1;
    bf16* ohp = dir ? m1h : m0h;
    bf16* olp = dir ? m1l : m0l;

    const int bh = blockIdx.y;
    const size_t base = (size_t)bh * LL * DDIM;
    const int q0 = blockIdx.x * 128;
    const int tid  = threadIdx.x;
    const int wid  = tid >> 5;
    const int lane = tid & 31;
    const int g  = lane >> 2;
    const int t4 = lane & 3;
    const int rb = lane & 15;
    const int chsel = lane >> 4;

    const u32 sQ  = sb;                 // 128 x 64 f16 = 16KB
    const u32 sStage = sb + 16384;      // 2 x (Kh 8KB + Vh 8KB)

    // load Q tile (128x64), swizzled rows of 128B
    #pragma unroll
    for (int rep = 0; rep < 2; rep++) {
        int idx = rep * 256 + tid;
        int row = idx >> 2, ch2 = idx & 3;
        #pragma unroll
        for (int s = 0; s < 2; s++) {
            int ch = ch2 * 2 + s;
            u32 soff = (u32)(row * 128 + ((ch ^ (row & 7)) << 4));
            *(uint4*)(smp + soff) =
                *(const uint4*)(qh + base + (size_t)(q0 + row) * DDIM + ch * 8);
        }
    }

    // prefetch indices for K/V (per thread: 2 chunks of K, 2 of V)
    const int pf_row = tid >> 2;        // 0..63
    const int pf_ch2 = tid & 3;

    // prefetch stage 0
    {
        u32 stg = sStage;
        #pragma unroll
        for (int s = 0; s < 2; s++) {
            int ch = pf_ch2 * 2 + s;
            u32 soff = (u32)(pf_row * 128 + ((ch ^ (pf_row & 7)) << 4));
            size_t goff = base + (size_t)pf_row * DDIM + ch * 8;
            CP_ASYNC16(stg + soff, (const char*)(kh + goff));
            CP_ASYNC16(stg + 8192 + soff, (const char*)(vh + goff));
        }
        CP_COMMIT();
    }
    __syncthreads();

    // Q fragments (per warp 16 rows, 4 k16 steps)
    u32 qf[4][4];
    {
        int qr = wid * 16 + rb;
        #pragma unroll
        for (int ks = 0; ks < 4; ks++) {
            int chunk = ks * 2 + chsel;
            u32 off = (u32)(qr * 128 + ((chunk ^ (qr & 7)) << 4));
            ldsm4(sQ + off, qf[ks][0], qf[ks][1], qf[ks][2], qf[ks][3]);
        }
    }

    float mrow0 = -1e30f, mrow1 = -1e30f, lrow0 = 0.f, lrow1 = 0.f;
    float oacc[8][4];
    #pragma unroll
    for (int dt = 0; dt < 8; dt++)
        #pragma unroll
        for (int t = 0; t < 4; t++) oacc[dt][t] = 0.f;

    for (int it = 0; it < 32; it++) {
        const u32 bufK = sStage + (u32)(it & 1) * 16384;
        const u32 bufV = bufK + 8192;

        if (it + 1 < 32) {
            u32 stg = sStage + (u32)((it + 1) & 1) * 16384;
            int k0n = (it + 1) * 64;
            #pragma unroll
            for (int s = 0; s < 2; s++) {
                int ch = pf_ch2 * 2 + s;
                u32 soff = (u32)(pf_row * 128 + ((ch ^ (pf_row & 7)) << 4));
                size_t goff = base + (size_t)(k0n + pf_row) * DDIM + ch * 8;
                CP_ASYNC16(stg + soff, (const char*)(kh + goff));
                CP_ASYNC16(stg + 8192 + soff, (const char*)(vh + goff));
            }
            CP_COMMIT();
            CP_WAIT1();
        } else {
            CP_WAIT0();
        }
        __syncthreads();

        // ---- S = Qh Kh^T (single pass) ----
        float acc[8][4];
        #pragma unroll
        for (int nt = 0; nt < 8; nt++)
            #pragma unroll
            for (int t = 0; t < 4; t++) acc[nt][t] = 0.f;

        #pragma unroll
        for (int ks = 0; ks < 4; ks++) {
            int chunk = ks * 2 + chsel;
            #pragma unroll
            for (int gg = 0; gg < 4; gg++) {
                int rr = gg * 16 + rb;
                u32 off = (u32)(rr * 128 + ((chunk ^ (rr & 7)) << 4));
                u32 r0, r1, r2, r3;
                ldsm4(bufK + off, r0, r1, r2, r3);
                { u32 bfa[2] = {r0, r2}; mma_f16(acc[2*gg],   qf[ks], bfa); }
                { u32 bfb[2] = {r1, r3}; mma_f16(acc[2*gg+1], qf[ks], bfb); }
            }
        }

        // ---- online softmax (rows g and g+8) ----
        float mx0 = -1e30f, mx1 = -1e30f;
        #pragma unroll
        for (int nt = 0; nt < 8; nt++) {
            mx0 = fmaxf(mx0, fmaxf(acc[nt][0], acc[nt][1]));
            mx1 = fmaxf(mx1, fmaxf(acc[nt][2], acc[nt][3]));
        }
        mx0 = fmaxf(mx0, __shfl_xor_sync(0xffffffffu, mx0, 1));
        mx0 = fmaxf(mx0, __shfl_xor_sync(0xffffffffu, mx0, 2));
        mx1 = fmaxf(mx1, __shfl_xor_sync(0xffffffffu, mx1, 1));
        mx1 = fmaxf(mx1, __shfl_xor_sync(0xffffffffu, mx1, 2));
        float mn0 = fmaxf(mrow0, mx0), mn1 = fmaxf(mrow1, mx1);
        float al0 = __expf(mrow0 - mn0), al1 = __expf(mrow1 - mn1);
        mrow0 = mn0; mrow1 = mn1;
        float s0 = 0.f, s1 = 0.f;
        #pragma unroll
        for (int nt = 0; nt < 8; nt++) {
            acc[nt][0] = __expf(acc[nt][0] - mn0);
            acc[nt][1] = __expf(acc[nt][1] - mn0);
            acc[nt][2] = __expf(acc[nt][2] - mn1);
            acc[nt][3] = __expf(acc[nt][3] - mn1);
            s0 += acc[nt][0] + acc[nt][1];
            s1 += acc[nt][2] + acc[nt][3];
        }
        s0 += __shfl_xor_sync(0xffffffffu, s0, 1);
        s0 += __shfl_xor_sync(0xffffffffu, s0, 2);
        s1 += __shfl_xor_sync(0xffffffffu, s1, 1);
        s1 += __shfl_xor_sync(0xffffffffu, s1, 2);
        lrow0 = lrow0 * al0 + s0;
        lrow1 = lrow1 * al1 + s1;
        #pragma unroll
        for (int dt = 0; dt < 8; dt++) {
            oacc[dt][0] *= al0; oacc[dt][1] *= al0;
            oacc[dt][2] *= al1; oacc[dt][3] *= al1;
        }

        // ---- pack P (C-frag -> A-frag) ----
        u32 ph[4][4];
        #pragma unroll
        for (int kb = 0; kb < 4; kb++) {
            ph[kb][0] = pack_h2(acc[2*kb][0],   acc[2*kb][1]);
            ph[kb][1] = pack_h2(acc[2*kb][2],   acc[2*kb][3]);
            ph[kb][2] = pack_h2(acc[2*kb+1][0], acc[2*kb+1][1]);
            ph[kb][3] = pack_h2(acc[2*kb+1][2], acc[2*kb+1][3]);
        }

        // ---- O += P V (single pass; V B-frags via trans ldsm) ----
        #pragma unroll
        for (int kb = 0; kb < 4; kb++) {
            int rr = kb * 16 + rb;
            #pragma unroll
            for (int dg = 0; dg < 4; dg++) {
                int chunk = dg * 2 + chsel;
                u32 off = (u32)(rr * 128 + ((chunk ^ (rr & 7)) << 4));
                u32 r0, r1, r2, r3;
                ldsm4t(bufV + off, r0, r1, r2, r3);
                { u32 vfa[2] = {r0, r1}; mma_f16(oacc[2*dg],   ph[kb], vfa); }
                { u32 vfb[2] = {r2, r3}; mma_f16(oacc[2*dg+1], ph[kb], vfb); }
            }
        }
        __syncthreads();
    }

    // ---- epilogue: normalize, split-store merged (B,L,C) ----
    float inv0 = 1.f / lrow0, inv1 = 1.f / lrow1;
    int r0g = q0 + wid * 16 + g;
    int bb = bh >> 2, hh = bh & 3;
    #pragma unroll
    for (int dt = 0; dt < 8; dt++) {
        int col = hh * DDIM + dt * 8 + t4 * 2;
        size_t o0 = (size_t)(bb * LL + r0g) * CC + col;
        size_t o1 = (size_t)(bb * LL + r0g + 8) * CC + col;
        u32 hi, lo;
        splitpack(oacc[dt][0] * inv0, oacc[dt][1] * inv0, hi, lo);
        *(u32*)(ohp + o0) = hi; *(u32*)(olp + o0) = lo;
        splitpack(oacc[dt][2] * inv1, oacc[dt][3] * inv1, hi, lo);
        *(u32*)(ohp + o1) = hi; *(u32*)(olp + o1) = lo;
    }
}

// ===================== LayerNorm + exact GELU -> split bf16 =====================
__global__ __launch_bounds__(256) void ln_gelu_kernel(
    const float* __restrict__ h0, const float* __restrict__ h1,
    bf16* __restrict__ h0h, bf16* __restrict__ h0l,
    bf16* __restrict__ h1h, bf16* __restrict__ h1l,
    const float* __restrict__ g, const float* __restrict__ bta)
{
    const float* hp = blockIdx.y ? h1 : h0;
    bf16* oh = blockIdx.y ? h1h : h0h;
    bf16* olo = blockIdx.y ? h1l : h0l;
    const size_t rowoff = (size_t)blockIdx.x * C2;
    const int tid = threadIdx.x;
    const int lane = tid & 31, wid = tid >> 5;

    float2 v = *(const float2*)&hp[rowoff + tid * 2];
    float s  = v.x + v.y;
    float sq = v.x * v.x + v.y * v.y;
    #pragma unroll
    for (int off = 16; off; off >>= 1) {
        s  += __shfl_xor_sync(0xffffffffu, s,  off);
        sq += __shfl_xor_sync(0xffffffffu, sq, off);
    }
    __shared__ float rs[8], rq[8];
    if (lane == 0) { rs[wid] = s; rq[wid] = sq; }
    __syncthreads();
    if (wid == 0) {
        s  = (lane < 8) ? rs[lane] : 0.f;
        sq = (lane < 8) ? rq[lane] : 0.f;
        #pragma unroll
        for (int off = 4; off; off >>= 1) {
            s  += __shfl_xor_sync(0xffffffffu, s,  off);
            sq += __shfl_xor_sync(0xffffffffu, sq, off);
        }
        if (lane == 0) { rs[0] = s; rq[0] = sq; }
    }
    __syncthreads();
    float mean = rs[0] * (1.f / 512.f);
    float var  = rq[0] * (1.f / 512.f) - mean * mean;
    float rstd = rsqrtf(var + 1e-5f);

    int c0 = tid * 2;
    float x0n = (v.x - mean) * rstd * g[c0]     + bta[c0];
    float x1n = (v.y - mean) * rstd * g[c0 + 1] + bta[c0 + 1];
    x0n = 0.5f * x0n * (1.f + erff(x0n * 0.70710678118654752f));
    x1n = 0.5f * x1n * (1.f + erff(x1n * 0.70710678118654752f));

    u32 hi, lo;
    splitpack(x0n, x1n, hi, lo);
    *(u32*)(oh + rowoff + c0)  = hi;
    *(u32*)(olo + rowoff + c0) = lo;
}

// ===================== launch =====================
extern "C" void kernel_launch(void* const* d_in, const int* in_sizes, int n_in,
                              void* d_out, int out_size)
{
    const float* x0   = (const float*)d_in[0];
    const float* x1   = (const float*)d_in[1];
    const float* Wqk  = (const float*)d_in[2];
    const float* bqk  = (const float*)d_in[3];
    const float* Wv   = (const float*)d_in[4];
    const float* bv   = (const float*)d_in[5];
    const float* Wout = (const float*)d_in[6];
    const float* bout = (const float*)d_in[7];
    const float* W1   = (const float*)d_in[8];
    const float* b1   = (const float*)d_in[9];
    const float* ln_g = (const float*)d_in[10];
    const float* ln_b = (const float*)d_in[11];
    const float* W2   = (const float*)d_in[12];
    const float* b2   = (const float*)d_in[13];
    float* out = (float*)d_out;

    float *p_h0, *p_h1;
    bf16 *px0h, *px0l, *px1h, *px1l;
    bf16 *pm0h, *pm0l, *pm1h, *pm1l;
    bf16 *pp0h, *pp0l, *pp1h, *pp1l;
    bf16 *ph0h, *ph0l, *ph1h, *ph1l;
    f16 *pq0, *pq1, *pv0, *pv1;
    bf16 *pWqkh, *pWqkl, *pWvh, *pWvl, *pWoth, *pWotl, *pW1h, *pW1l, *pW2h, *pW2l;

    cudaGetSymbolAddress((void**)&p_h0,  g_h0);
    cudaGetSymbolAddress((void**)&p_h1,  g_h1);
    cudaGetSymbolAddress((void**)&px0h, g_x0h); cudaGetSymbolAddress((void**)&px0l, g_x0l);
    cudaGetSymbolAddress((void**)&px1h, g_x1h); cudaGetSymbolAddress((void**)&px1l, g_x1l);
    cudaGetSymbolAddress((void**)&pm0h, g_m0h); cudaGetSymbolAddress((void**)&pm0l, g_m0l);
    cudaGetSymbolAddress((void**)&pm1h, g_m1h); cudaGetSymbolAddress((void**)&pm1l, g_m1l);
    cudaGetSymbolAddress((void**)&pp0h, g_p0h); cudaGetSymbolAddress((void**)&pp0l, g_p0l);
    cudaGetSymbolAddress((void**)&pp1h, g_p1h); cudaGetSymbolAddress((void**)&pp1l, g_p1l);
    cudaGetSymbolAddress((void**)&ph0h, g_h0h); cudaGetSymbolAddress((void**)&ph0l, g_h0l);
    cudaGetSymbolAddress((void**)&ph1h, g_h1h); cudaGetSymbolAddress((void**)&ph1l, g_h1l);
    cudaGetSymbolAddress((void**)&pq0, g_qk0); cudaGetSymbolAddress((void**)&pq1, g_qk1);
    cudaGetSymbolAddress((void**)&pv0, g_v0);  cudaGetSymbolAddress((void**)&pv1, g_v1);
    cudaGetSymbolAddress((void**)&pWqkh, g_Wqkh); cudaGetSymbolAddress((void**)&pWqkl, g_Wqkl);
    cudaGetSymbolAddress((void**)&pWvh,  g_Wvh);  cudaGetSymbolAddress((void**)&pWvl,  g_Wvl);
    cudaGetSymbolAddress((void**)&pWoth, g_Woth); cudaGetSymbolAddress((void**)&pWotl, g_Wotl);
    cudaGetSymbolAddress((void**)&pW1h,  g_W1h);  cudaGetSymbolAddress((void**)&pW1l,  g_W1l);
    cudaGetSymbolAddress((void**)&pW2h,  g_W2h);  cudaGetSymbolAddress((void**)&pW2l,  g_W2l);

    cudaFuncSetAttribute(mma_gemm,
                         cudaFuncAttributeMaxDynamicSharedMemorySize, MG_SMEM);
    cudaFuncSetAttribute(flash_mma,
                         cudaFuncAttributeMaxDynamicSharedMemorySize, FK_SMEM);

    const float qscale = 0.35355339059327373f; // 64^-0.25

    split_kernel<<<RR * CC / 1024, 256>>>(x0, px0h, px0l, RR * CC);
    split_kernel<<<RR * CC / 1024, 256>>>(x1, px1h, px1l, RR * CC);
    wsplit_kernel<<<dim3(CC/32, CC/32), dim3(32,8)>>>(Wqk,  pWqkh, pWqkl, CC, CC);
    wsplit_kernel<<<dim3(CC/32, CC/32), dim3(32,8)>>>(Wv,   pWvh,  pWvl,  CC, CC);
    wsplit_kernel<<<dim3(CC/32, CC/32), dim3(32,8)>>>(Wout, pWoth, pWotl, CC, CC);
    wsplit_kernel<<<dim3(C2/32, C2/32), dim3(32,8)>>>(W1,   pW1h,  pW1l,  C2, C2);
    wsplit_kernel<<<dim3(CC/32, C2/32), dim3(32,8)>>>(W2,   pW2h,  pW2l,  C2, CC);

    dim3 g256(2, 128);
    dim3 g512(4, 128);

    // QK / V projections -> fp16 head layout (mode 3)
    mma_gemm<<<g256, 256, MG_SMEM>>>(px0h, px0l, CC, nullptr, nullptr, 0,
        pWqkh, pWqkl, bqk, nullptr, nullptr, nullptr, nullptr, pq0, CC, qscale, 3);
    mma_gemm<<<g256, 256, MG_SMEM>>>(px1h, px1l, CC, nullptr, nullptr, 0,
        pWqkh, pWqkl, bqk, nullptr, nullptr, nullptr, nullptr, pq1, CC, qscale, 3);
    mma_gemm<<<g256, 256, MG_SMEM>>>(px0h, px0l, CC, nullptr, nullptr, 0,
        pWvh, pWvl, bv, nullptr, nullptr, nullptr, nullptr, pv0, CC, 1.f, 3);
    mma_gemm<<<g256, 256, MG_SMEM>>>(px1h, px1l, CC, nullptr, nullptr, 0,
        pWvh, pWvl, bv, nullptr, nullptr, nullptr, nullptr, pv1, CC, 1.f, 3);

    // dual flash attention -> split bf16 merged
    dim3 fg(LL / 128, BB * HH, 2);
    flash_mma<<<fg, 256, FK_SMEM>>>(pq0, pq1, pv0, pv1,
                                    pm0h, pm0l, pm1h, pm1l);

    // output projection -> split bf16
    mma_gemm<<<g256, 256, MG_SMEM>>>(pm0h, pm0l, CC, nullptr, nullptr, 0,
        pWoth, pWotl, bout, nullptr, nullptr, pp0h, pp0l, nullptr, CC, 1.f, 2);
    mma_gemm<<<g256, 256, MG_SMEM>>>(pm1h, pm1l, CC, nullptr, nullptr, 0,
        pWoth, pWotl, bout, nullptr, nullptr, pp1h, pp1l, nullptr, CC, 1.f, 2);

    // FFN-1 on virtual concat([x, p]) -> f32
    mma_gemm<<<g512, 256, MG_SMEM>>>(px0h, px0l, CC, pp0h, pp0l, CC,
        pW1h, pW1l, b1, nullptr, p_h0, nullptr, nullptr, nullptr, C2, 1.f, 0);
    mma_gemm<<<g512, 256, MG_SMEM>>>(px1h, px1l, CC, pp1h, pp1l, CC,
        pW1h, pW1l, b1, nullptr, p_h1, nullptr, nullptr, nullptr, C2, 1.f, 0);

    // LayerNorm + GELU -> split bf16
    dim3 lg(RR, 2);
    ln_gelu_kernel<<<lg, 256>>>(p_h0, p_h1, ph0h, ph0l, ph1h, ph1l, ln_g, ln_b);

    // FFN-2 + residual -> outputs
    mma_gemm<<<g256, 256, MG_SMEM>>>(ph0h, ph0l, C2, nullptr, nullptr, 0,
        pW2h, pW2l, b2, x0, out, nullptr, nullptr, nullptr, CC, 1.f, 0);
    mma_gemm<<<g256, 256, MG_SMEM>>>(ph1h, ph1l, C2, nullptr, nullptr, 0,
        pW2h, pW2l, b2, x1, out + (size_t)RR * CC, nullptr, nullptr, nullptr, CC, 1.f, 0);
}

// round 9
// speedup vs baseline: 2.7540x; 1.0471x over previous
#include <cuda_runtime.h>
#include <cuda_bf16.h>
#include <cuda_fp16.h>
#include <math.h>
#include <stdint.h>

#define BB 8
#define LL 2048
#define CC 256
#define HH 4
#define DDIM 64
#define RR (BB*LL)
#define C2 (2*CC)
#define SHIFT 4.0f

typedef unsigned long long u64;
typedef unsigned int u32;
typedef __nv_bfloat16 bf16;
typedef __half f16;

__device__ __forceinline__ void split1(float x, bf16& h_, bf16& l_) {
    h_ = __float2bfloat16(x);
    l_ = __float2bfloat16(x - __bfloat162float(h_));
}
__device__ __forceinline__ void splitpack(float a, float b, u32& hi, u32& lo) {
    bf16 ah, al, bh_, bl_;
    split1(a, ah, al); split1(b, bh_, bl_);
    __nv_bfloat162 th, tl;
    th.x = ah; th.y = bh_; tl.x = al; tl.y = bl_;
    hi = *(u32*)&th; lo = *(u32*)&tl;
}
__device__ __forceinline__ u32 pack_h2(float a, float b) {
    __half2 t = __halves2half2(__float2half_rn(a), __float2half_rn(b));
    return *(u32*)&t;
}
__device__ __forceinline__ u32 smem_u32(const void* p) {
    u32 a;
    asm("{ .reg .u64 t; cvta.to.shared.u64 t, %1; cvt.u32.u64 %0, t; }"
        : "=r"(a) : "l"(p));
    return a;
}
__device__ __forceinline__ void ldsm4(u32 addr, u32& r0, u32& r1, u32& r2, u32& r3) {
    asm volatile("ldmatrix.sync.aligned.m8n8.x4.shared.b16 {%0,%1,%2,%3}, [%4];"
                 : "=r"(r0), "=r"(r1), "=r"(r2), "=r"(r3) : "r"(addr));
}
__device__ __forceinline__ void ldsm4t(u32 addr, u32& r0, u32& r1, u32& r2, u32& r3) {
    asm volatile("ldmatrix.sync.aligned.m8n8.x4.trans.shared.b16 {%0,%1,%2,%3}, [%4];"
                 : "=r"(r0), "=r"(r1), "=r"(r2), "=r"(r3) : "r"(addr));
}
__device__ __forceinline__ void mma_bf16(float* c, const u32* a, const u32* b) {
    asm volatile(
        "mma.sync.aligned.m16n8k16.row.col.f32.bf16.bf16.f32 "
        "{%0,%1,%2,%3},{%4,%5,%6,%7},{%8,%9},{%0,%1,%2,%3};"
        : "+f"(c[0]), "+f"(c[1]), "+f"(c[2]), "+f"(c[3])
        : "r"(a[0]), "r"(a[1]), "r"(a[2]), "r"(a[3]), "r"(b[0]), "r"(b[1]));
}
__device__ __forceinline__ void mma_f16(float* c, const u32* a, const u32* b) {
    asm volatile(
        "mma.sync.aligned.m16n8k16.row.col.f32.f16.f16.f32 "
        "{%0,%1,%2,%3},{%4,%5,%6,%7},{%8,%9},{%0,%1,%2,%3};"
        : "+f"(c[0]), "+f"(c[1]), "+f"(c[2]), "+f"(c[3])
        : "r"(a[0]), "r"(a[1]), "r"(a[2]), "r"(a[3]), "r"(b[0]), "r"(b[1]));
}
#define CP_ASYNC16(smem, gptr) \
    asm volatile("cp.async.cg.shared.global [%0], [%1], 16;" \
                 :: "r"(smem), "l"(gptr) : "memory")
#define CP_COMMIT() asm volatile("cp.async.commit_group;" ::: "memory")
#define CP_WAIT1()  asm volatile("cp.async.wait_group 1;" ::: "memory")
#define CP_WAIT0()  asm volatile("cp.async.wait_group 0;" ::: "memory")

// ===================== scratch =====================
__device__ float g_h0 [RR*C2];
__device__ float g_h1 [RR*C2];

__device__ bf16 g_x0h[RR*CC], g_x0l[RR*CC], g_x1h[RR*CC], g_x1l[RR*CC];
__device__ bf16 g_m0h[RR*CC], g_m0l[RR*CC], g_m1h[RR*CC], g_m1l[RR*CC];
__device__ bf16 g_p0h[RR*CC], g_p0l[RR*CC], g_p1h[RR*CC], g_p1l[RR*CC];
__device__ bf16 g_h0h[RR*C2], g_h0l[RR*C2], g_h1h[RR*C2], g_h1l[RR*C2];

__device__ f16 g_qk0[BB*HH*LL*DDIM];
__device__ f16 g_qk1[BB*HH*LL*DDIM];
__device__ f16 g_v0 [BB*HH*LL*DDIM];
__device__ f16 g_v1 [BB*HH*LL*DDIM];

__device__ bf16 g_Wqkh[CC*CC], g_Wqkl[CC*CC];
__device__ bf16 g_Wvh [CC*CC], g_Wvl [CC*CC];
__device__ bf16 g_Woth[CC*CC], g_Wotl[CC*CC];
__device__ bf16 g_W1h [C2*C2], g_W1l [C2*C2];
__device__ bf16 g_W2h [CC*C2], g_W2l [CC*C2];

// ===================== split f32 -> bf16 hi/lo =====================
__global__ __launch_bounds__(256) void split_kernel(
    const float* __restrict__ x, bf16* __restrict__ hi, bf16* __restrict__ lo, int n)
{
    int i = (blockIdx.x * 256 + threadIdx.x) * 4;
    if (i >= n) return;
    float4 v = *(const float4*)(x + i);
    uint2 uh, ul;
    splitpack(v.x, v.y, uh.x, ul.x);
    splitpack(v.z, v.w, uh.y, ul.y);
    *(uint2*)(hi + i) = uh;
    *(uint2*)(lo + i) = ul;
}

// ===================== transpose W [K,N] -> split [N,K] =====================
__global__ __launch_bounds__(256) void wsplit_kernel(
    const float* __restrict__ W, bf16* __restrict__ hi, bf16* __restrict__ lo,
    int K, int N)
{
    __shared__ float t[32][33];
    int nb = blockIdx.x * 32, kb = blockIdx.y * 32;
    int tx = threadIdx.x, ty0 = threadIdx.y;
    #pragma unroll
    for (int r = 0; r < 4; r++) {
        int ty = ty0 + r * 8;
        t[ty][tx] = W[(size_t)(kb + ty) * N + nb + tx];
    }
    __syncthreads();
    #pragma unroll
    for (int r = 0; r < 4; r++) {
        int ty = ty0 + r * 8;
        float v = t[tx][ty];
        bf16 h_, l_;
        split1(v, h_, l_);
        size_t o = (size_t)(nb + ty) * K + kb + tx;
        hi[o] = h_; lo[o] = l_;
    }
}

// ===================== mma.sync split-bf16 GEMM =====================
// mode: 0 = f32 out (+res), 2 = split bf16 out, 3 = fp16 head-layout
#define MG_SMEM (64*1024 + 128)

__global__ __launch_bounds__(256, 2) void mma_gemm(
    const bf16* __restrict__ a0h, const bf16* __restrict__ a0l, int K0,
    const bf16* __restrict__ a1h, const bf16* __restrict__ a1l, int K1,
    const bf16* __restrict__ bh, const bf16* __restrict__ bl,
    const float* __restrict__ bias,
    const float* __restrict__ res,
    float* __restrict__ outf,
    bf16* __restrict__ outh, bf16* __restrict__ outl,
    f16* __restrict__ outfh,
    int N, float scale, int mode)
{
    extern __shared__ char dsm[];
    u32 sb0 = smem_u32(dsm);
    u32 sb  = (sb0 + 127) & ~127u;
    char* smp = dsm + (sb - sb0);

    const int tid  = threadIdx.x;
    const int wid  = tid >> 5;
    const int lane = tid & 31;

    const int m0 = blockIdx.y * 128;
    const int n0 = blockIdx.x * 128;
    const int KB = K0 + K1;
    const int nc0 = K0 >> 6;
    const int nc  = KB >> 6;

    const int wm = (wid >> 2) * 64;
    const int wn = (wid & 3) * 32;

    const u32 sAh = sb;
    const u32 sAl = sb + 16384;
    const u32 sBh = sb + 32768;
    const u32 sBl = sb + 49152;

    float acc[4][4][4];
    #pragma unroll
    for (int i = 0; i < 4; i++)
        #pragma unroll
        for (int j = 0; j < 4; j++)
            #pragma unroll
            for (int t = 0; t < 4; t++) acc[i][j][t] = 0.f;

    const int ld_row = tid >> 3;
    const int ld_ch  = tid & 7;

    for (int c = 0; c < nc; c++) {
        __syncthreads();
        const bf16 *Ah, *Al;
        int astr, koff;
        if (c < nc0) { Ah = a0h; Al = a0l; astr = K0; koff = c << 6; }
        else         { Ah = a1h; Al = a1l; astr = K1; koff = (c - nc0) << 6; }
        const int koffB = c << 6;

        #pragma unroll
        for (int i = 0; i < 4; i++) {
            int row = ld_row + i * 32;
            u32 off = (u32)(row * 128 + ((ld_ch ^ (row & 7)) << 4));
            *(uint4*)(smp + off) =
                *(const uint4*)(Ah + (size_t)(m0 + row) * astr + koff + ld_ch * 8);
            *(uint4*)(smp + 16384 + off) =
                *(const uint4*)(Al + (size_t)(m0 + row) * astr + koff + ld_ch * 8);
            *(uint4*)(smp + 32768 + off) =
                *(const uint4*)(bh + (size_t)(n0 + row) * KB + koffB + ld_ch * 8);
            *(uint4*)(smp + 49152 + off) =
                *(const uint4*)(bl + (size_t)(n0 + row) * KB + koffB + ld_ch * 8);
        }
        __syncthreads();

        #pragma unroll
        for (int ks = 0; ks < 4; ks++) {
            const int cidx = ks * 2 + (lane >> 4);
            u32 bfh[4][2], bfl[4][2];
            #pragma unroll
            for (int g = 0; g < 2; g++) {
                int rb = wn + g * 16 + (lane & 15);
                u32 off = (u32)(rb * 128 + ((cidx ^ (rb & 7)) << 4));
                u32 r0, r1, r2, r3;
                ldsm4(sBh + off, r0, r1, r2, r3);
                bfh[2*g][0] = r0; bfh[2*g][1] = r2;
                bfh[2*g+1][0] = r1; bfh[2*g+1][1] = r3;
                ldsm4(sBl + off, r0, r1, r2, r3);
                bfl[2*g][0] = r0; bfl[2*g][1] = r2;
                bfl[2*g+1][0] = r1; bfl[2*g+1][1] = r3;
            }
            u32 af[4][4];
            #pragma unroll
            for (int mi = 0; mi < 4; mi++) {
                int ra = wm + mi * 16 + (lane & 15);
                u32 off = (u32)(ra * 128 + ((cidx ^ (ra & 7)) << 4));
                ldsm4(sAh + off, af[mi][0], af[mi][1], af[mi][2], af[mi][3]);
            }
            #pragma unroll
            for (int mi = 0; mi < 4; mi++)
                #pragma unroll
                for (int nj = 0; nj < 4; nj++)
                    mma_bf16(acc[mi][nj], af[mi], bfh[nj]);
            #pragma unroll
            for (int mi = 0; mi < 4; mi++)
                #pragma unroll
                for (int nj = 0; nj < 4; nj++)
                    mma_bf16(acc[mi][nj], af[mi], bfl[nj]);
            #pragma unroll
            for (int mi = 0; mi < 4; mi++) {
                int ra = wm + mi * 16 + (lane & 15);
                u32 off = (u32)(ra * 128 + ((cidx ^ (ra & 7)) << 4));
                ldsm4(sAl + off, af[mi][0], af[mi][1], af[mi][2], af[mi][3]);
            }
            #pragma unroll
            for (int mi = 0; mi < 4; mi++)
                #pragma unroll
                for (int nj = 0; nj < 4; nj++)
                    mma_bf16(acc[mi][nj], af[mi], bfh[nj]);
        }
    }

    const int lr = lane >> 2;
    const int lc = (lane & 3) * 2;
    #pragma unroll
    for (int mi = 0; mi < 4; mi++) {
        #pragma unroll
        for (int half = 0; half < 2; half++) {
            int r = m0 + wm + mi * 16 + lr + half * 8;
            #pragma unroll
            for (int nj = 0; nj < 4; nj++) {
                int col = n0 + wn + nj * 8 + lc;
                float2 bv = *(const float2*)(bias + col);
                float v0 = (acc[mi][nj][half * 2]     + bv.x) * scale;
                float v1 = (acc[mi][nj][half * 2 + 1] + bv.y) * scale;
                if (mode == 0) {
                    size_t o = (size_t)r * N + col;
                    if (res) {
                        float2 rv = *(const float2*)(res + o);
                        v0 += rv.x; v1 += rv.y;
                    }
                    *(float2*)(outf + o) = make_float2(v0, v1);
                } else if (mode == 2) {
                    size_t o = (size_t)r * N + col;
                    u32 hi, lo;
                    splitpack(v0, v1, hi, lo);
                    *(u32*)(outh + o) = hi;
                    *(u32*)(outl + o) = lo;
                } else { // mode 3: head-layout fp16
                    int b_ = r >> 11, l = r & 2047;
                    int h  = col >> 6, d = col & 63;
                    size_t o = (((size_t)(b_ * HH + h)) * LL + l) * DDIM + d;
                    *(u32*)(outfh + o) = pack_h2(v0, v1);
                }
            }
        }
    }
}

// ===================== flash attention (fp16, fixed-shift softmax, cp.async) =====================
#define FK_SMEM (48*1024 + 128)

__global__ __launch_bounds__(256, 2) void flash_mma(
    const f16* __restrict__ qk0, const f16* __restrict__ qk1,
    const f16* __restrict__ v0,  const f16* __restrict__ v1,
    bf16* __restrict__ m0h, bf16* __restrict__ m0l,
    bf16* __restrict__ m1h, bf16* __restrict__ m1l)
{
    extern __shared__ char dsm[];
    u32 sb0 = smem_u32(dsm);
    u32 sb  = (sb0 + 127) & ~127u;
    char* smp = dsm + (sb - sb0);

    const int dir = blockIdx.z;
    const f16* qh = dir ? qk1 : qk0;
    const f16* kh = dir ? qk0 : qk1;
    const f16* vh = dir ? v0 : v1;
    bf16* ohp = dir ? m1h : m0h;
    bf16* olp = dir ? m1l : m0l;

    const int bh = blockIdx.y;
    const size_t base = (size_t)bh * LL * DDIM;
    const int q0 = blockIdx.x * 128;
    const int tid  = threadIdx.x;
    const int wid  = tid >> 5;
    const int lane = tid & 31;
    const int g  = lane >> 2;
    const int t4 = lane & 3;
    const int rb = lane & 15;
    const int chsel = lane >> 4;

    const u32 sQ  = sb;
    const u32 sStage = sb + 16384;

    #pragma unroll
    for (int rep = 0; rep < 2; rep++) {
        int idx = rep * 256 + tid;
        int row = idx >> 2, ch2 = idx & 3;
        #pragma unroll
        for (int s = 0; s < 2; s++) {
            int ch = ch2 * 2 + s;
            u32 soff = (u32)(row * 128 + ((ch ^ (row & 7)) << 4));
            *(uint4*)(smp + soff) =
                *(const uint4*)(qh + base + (size_t)(q0 + row) * DDIM + ch * 8);
        }
    }

    const int pf_row = tid >> 2;
    const int pf_ch2 = tid & 3;

    {
        u32 stg = sStage;
        #pragma unroll
        for (int s = 0; s < 2; s++) {
            int ch = pf_ch2 * 2 + s;
            u32 soff = (u32)(pf_row * 128 + ((ch ^ (pf_row & 7)) << 4));
            size_t goff = base + (size_t)pf_row * DDIM + ch * 8;
            CP_ASYNC16(stg + soff, (const char*)(kh + goff));
            CP_ASYNC16(stg + 8192 + soff, (const char*)(vh + goff));
        }
        CP_COMMIT();
    }
    __syncthreads();

    u32 qf[4][4];
    {
        int qr = wid * 16 + rb;
        #pragma unroll
        for (int ks = 0; ks < 4; ks++) {
            int chunk = ks * 2 + chsel;
            u32 off = (u32)(qr * 128 + ((chunk ^ (qr & 7)) << 4));
            ldsm4(sQ + off, qf[ks][0], qf[ks][1], qf[ks][2], qf[ks][3]);
        }
    }

    float lrow0 = 0.f, lrow1 = 0.f;
    float oacc[8][4];
    #pragma unroll
    for (int dt = 0; dt < 8; dt++)
        #pragma unroll
        for (int t = 0; t < 4; t++) oacc[dt][t] = 0.f;

    for (int it = 0; it < 32; it++) {
        const u32 bufK = sStage + (u32)(it & 1) * 16384;
        const u32 bufV = bufK + 8192;

        if (it + 1 < 32) {
            u32 stg = sStage + (u32)((it + 1) & 1) * 16384;
            int k0n = (it + 1) * 64;
            #pragma unroll
            for (int s = 0; s < 2; s++) {
                int ch = pf_ch2 * 2 + s;
                u32 soff = (u32)(pf_row * 128 + ((ch ^ (pf_row & 7)) << 4));
                size_t goff = base + (size_t)(k0n + pf_row) * DDIM + ch * 8;
                CP_ASYNC16(stg + soff, (const char*)(kh + goff));
                CP_ASYNC16(stg + 8192 + soff, (const char*)(vh + goff));
            }
            CP_COMMIT();
            CP_WAIT1();
        } else {
            CP_WAIT0();
        }
        __syncthreads();

        float acc[8][4];
        #pragma unroll
        for (int nt = 0; nt < 8; nt++)
            #pragma unroll
            for (int t = 0; t < 4; t++) acc[nt][t] = 0.f;

        #pragma unroll
        for (int ks = 0; ks < 4; ks++) {
            int chunk = ks * 2 + chsel;
            #pragma unroll
            for (int gg = 0; gg < 4; gg++) {
                int rr = gg * 16 + rb;
                u32 off = (u32)(rr * 128 + ((chunk ^ (rr & 7)) << 4));
                u32 r0, r1, r2, r3;
                ldsm4(bufK + off, r0, r1, r2, r3);
                { u32 bfa[2] = {r0, r2}; mma_f16(acc[2*gg],   qf[ks], bfa); }
                { u32 bfb[2] = {r1, r3}; mma_f16(acc[2*gg+1], qf[ks], bfb); }
            }
        }

        // P = exp(S - SHIFT); local row-sum accumulation (reduced once at end)
        u32 ph[4][4];
        #pragma unroll
        for (int nt = 0; nt < 8; nt++) {
            acc[nt][0] = __expf(acc[nt][0] - SHIFT);
            acc[nt][1] = __expf(acc[nt][1] - SHIFT);
            acc[nt][2] = __expf(acc[nt][2] - SHIFT);
            acc[nt][3] = __expf(acc[nt][3] - SHIFT);
            lrow0 += acc[nt][0] + acc[nt][1];
            lrow1 += acc[nt][2] + acc[nt][3];
        }
        #pragma unroll
        for (int kb = 0; kb < 4; kb++) {
            ph[kb][0] = pack_h2(acc[2*kb][0],   acc[2*kb][1]);
            ph[kb][1] = pack_h2(acc[2*kb][2],   acc[2*kb][3]);
            ph[kb][2] = pack_h2(acc[2*kb+1][0], acc[2*kb+1][1]);
            ph[kb][3] = pack_h2(acc[2*kb+1][2], acc[2*kb+1][3]);
        }

        #pragma unroll
        for (int kb = 0; kb < 4; kb++) {
            int rr = kb * 16 + rb;
            #pragma unroll
            for (int dg = 0; dg < 4; dg++) {
                int chunk = dg * 2 + chsel;
                u32 off = (u32)(rr * 128 + ((chunk ^ (rr & 7)) << 4));
                u32 r0, r1, r2, r3;
                ldsm4t(bufV + off, r0, r1, r2, r3);
                { u32 vfa[2] = {r0, r1}; mma_f16(oacc[2*dg],   ph[kb], vfa); }
                { u32 vfb[2] = {r2, r3}; mma_f16(oacc[2*dg+1], ph[kb], vfb); }
            }
        }
        __syncthreads();
    }

    lrow0 += __shfl_xor_sync(0xffffffffu, lrow0, 1);
    lrow0 += __shfl_xor_sync(0xffffffffu, lrow0, 2);
    lrow1 += __shfl_xor_sync(0xffffffffu, lrow1, 1);
    lrow1 += __shfl_xor_sync(0xffffffffu, lrow1, 2);

    float inv0 = 1.f / lrow0, inv1 = 1.f / lrow1;
    int r0g = q0 + wid * 16 + g;
    int bb = bh >> 2, hh = bh & 3;
    #pragma unroll
    for (int dt = 0; dt < 8; dt++) {
        int col = hh * DDIM + dt * 8 + t4 * 2;
        size_t o0 = (size_t)(bb * LL + r0g) * CC + col;
        size_t o1 = (size_t)(bb * LL + r0g + 8) * CC + col;
        u32 hi, lo;
        splitpack(oacc[dt][0] * inv0, oacc[dt][1] * inv0, hi, lo);
        *(u32*)(ohp + o0) = hi; *(u32*)(olp + o0) = lo;
        splitpack(oacc[dt][2] * inv1, oacc[dt][3] * inv1, hi, lo);
        *(u32*)(ohp + o1) = hi; *(u32*)(olp + o1) = lo;
    }
}

// ===================== LayerNorm + exact GELU -> split bf16 =====================
__global__ __launch_bounds__(256) void ln_gelu_kernel(
    const float* __restrict__ h0, const float* __restrict__ h1,
    bf16* __restrict__ h0h, bf16* __restrict__ h0l,
    bf16* __restrict__ h1h, bf16* __restrict__ h1l,
    const float* __restrict__ g, const float* __restrict__ bta)
{
    const float* hp = blockIdx.y ? h1 : h0;
    bf16* oh = blockIdx.y ? h1h : h0h;
    bf16* olo = blockIdx.y ? h1l : h0l;
    const size_t rowoff = (size_t)blockIdx.x * C2;
    const int tid = threadIdx.x;
    const int lane = tid & 31, wid = tid >> 5;

    float2 v = *(const float2*)&hp[rowoff + tid * 2];
    float s  = v.x + v.y;
    float sq = v.x * v.x + v.y * v.y;
    #pragma unroll
    for (int off = 16; off; off >>= 1) {
        s  += __shfl_xor_sync(0xffffffffu, s,  off);
        sq += __shfl_xor_sync(0xffffffffu, sq, off);
    }
    __shared__ float rs[8], rq[8];
    if (lane == 0) { rs[wid] = s; rq[wid] = sq; }
    __syncthreads();
    if (wid == 0) {
        s  = (lane < 8) ? rs[lane] : 0.f;
        sq = (lane < 8) ? rq[lane] : 0.f;
        #pragma unroll
        for (int off = 4; off; off >>= 1) {
            s  += __shfl_xor_sync(0xffffffffu, s,  off);
            sq += __shfl_xor_sync(0xffffffffu, sq, off);
        }
        if (lane == 0) { rs[0] = s; rq[0] = sq; }
    }
    __syncthreads();
    float mean = rs[0] * (1.f / 512.f);
    float var  = rq[0] * (1.f / 512.f) - mean * mean;
    float rstd = rsqrtf(var + 1e-5f);

    int c0 = tid * 2;
    float x0n = (v.x - mean) * rstd * g[c0]     + bta[c0];
    float x1n = (v.y - mean) * rstd * g[c0 + 1] + bta[c0 + 1];
    x0n = 0.5f * x0n * (1.f + erff(x0n * 0.70710678118654752f));
    x1n = 0.5f * x1n * (1.f + erff(x1n * 0.70710678118654752f));

    u32 hi, lo;
    splitpack(x0n, x1n, hi, lo);
    *(u32*)(oh + rowoff + c0)  = hi;
    *(u32*)(olo + rowoff + c0) = lo;
}

// ===================== launch =====================
extern "C" void kernel_launch(void* const* d_in, const int* in_sizes, int n_in,
                              void* d_out, int out_size)
{
    const float* x0   = (const float*)d_in[0];
    const float* x1   = (const float*)d_in[1];
    const float* Wqk  = (const float*)d_in[2];
    const float* bqk  = (const float*)d_in[3];
    const float* Wv   = (const float*)d_in[4];
    const float* bv   = (const float*)d_in[5];
    const float* Wout = (const float*)d_in[6];
    const float* bout = (const float*)d_in[7];
    const float* W1   = (const float*)d_in[8];
    const float* b1   = (const float*)d_in[9];
    const float* ln_g = (const float*)d_in[10];
    const float* ln_b = (const float*)d_in[11];
    const float* W2   = (const float*)d_in[12];
    const float* b2   = (const float*)d_in[13];
    float* out = (float*)d_out;

    float *p_h0, *p_h1;
    bf16 *px0h, *px0l, *px1h, *px1l;
    bf16 *pm0h, *pm0l, *pm1h, *pm1l;
    bf16 *pp0h, *pp0l, *pp1h, *pp1l;
    bf16 *ph0h, *ph0l, *ph1h, *ph1l;
    f16 *pq0, *pq1, *pv0, *pv1;
    bf16 *pWqkh, *pWqkl, *pWvh, *pWvl, *pWoth, *pWotl, *pW1h, *pW1l, *pW2h, *pW2l;

    cudaGetSymbolAddress((void**)&p_h0,  g_h0);
    cudaGetSymbolAddress((void**)&p_h1,  g_h1);
    cudaGetSymbolAddress((void**)&px0h, g_x0h); cudaGetSymbolAddress((void**)&px0l, g_x0l);
    cudaGetSymbolAddress((void**)&px1h, g_x1h); cudaGetSymbolAddress((void**)&px1l, g_x1l);
    cudaGetSymbolAddress((void**)&pm0h, g_m0h); cudaGetSymbolAddress((void**)&pm0l, g_m0l);
    cudaGetSymbolAddress((void**)&pm1h, g_m1h); cudaGetSymbolAddress((void**)&pm1l, g_m1l);
    cudaGetSymbolAddress((void**)&pp0h, g_p0h); cudaGetSymbolAddress((void**)&pp0l, g_p0l);
    cudaGetSymbolAddress((void**)&pp1h, g_p1h); cudaGetSymbolAddress((void**)&pp1l, g_p1l);
    cudaGetSymbolAddress((void**)&ph0h, g_h0h); cudaGetSymbolAddress((void**)&ph0l, g_h0l);
    cudaGetSymbolAddress((void**)&ph1h, g_h1h); cudaGetSymbolAddress((void**)&ph1l, g_h1l);
    cudaGetSymbolAddress((void**)&pq0, g_qk0); cudaGetSymbolAddress((void**)&pq1, g_qk1);
    cudaGetSymbolAddress((void**)&pv0, g_v0);  cudaGetSymbolAddress((void**)&pv1, g_v1);
    cudaGetSymbolAddress((void**)&pWqkh, g_Wqkh); cudaGetSymbolAddress((void**)&pWqkl, g_Wqkl);
    cudaGetSymbolAddress((void**)&pWvh,  g_Wvh);  cudaGetSymbolAddress((void**)&pWvl,  g_Wvl);
    cudaGetSymbolAddress((void**)&pWoth, g_Woth); cudaGetSymbolAddress((void**)&pWotl, g_Wotl);
    cudaGetSymbolAddress((void**)&pW1h,  g_W1h);  cudaGetSymbolAddress((void**)&pW1l,  g_W1l);
    cudaGetSymbolAddress((void**)&pW2h,  g_W2h);  cudaGetSymbolAddress((void**)&pW2l,  g_W2l);

    cudaFuncSetAttribute(mma_gemm,
                         cudaFuncAttributeMaxDynamicSharedMemorySize, MG_SMEM);
    cudaFuncSetAttribute(flash_mma,
                         cudaFuncAttributeMaxDynamicSharedMemorySize, FK_SMEM);

    const float qscale = 0.35355339059327373f; // 64^-0.25

    split_kernel<<<RR * CC / 1024, 256>>>(x0, px0h, px0l, RR * CC);
    split_kernel<<<RR * CC / 1024, 256>>>(x1, px1h, px1l, RR * CC);
    wsplit_kernel<<<dim3(CC/32, CC/32), dim3(32,8)>>>(Wqk,  pWqkh, pWqkl, CC, CC);
    wsplit_kernel<<<dim3(CC/32, CC/32), dim3(32,8)>>>(Wv,   pWvh,  pWvl,  CC, CC);
    wsplit_kernel<<<dim3(CC/32, CC/32), dim3(32,8)>>>(Wout, pWoth, pWotl, CC, CC);
    wsplit_kernel<<<dim3(C2/32, C2/32), dim3(32,8)>>>(W1,   pW1h,  pW1l,  C2, C2);
    wsplit_kernel<<<dim3(CC/32, C2/32), dim3(32,8)>>>(W2,   pW2h,  pW2l,  C2, CC);

    dim3 g256(2, 128);
    dim3 g512(4, 128);

    mma_gemm<<<g256, 256, MG_SMEM>>>(px0h, px0l, CC, nullptr, nullptr, 0,
        pWqkh, pWqkl, bqk, nullptr, nullptr, nullptr, nullptr, pq0, CC, qscale, 3);
    mma_gemm<<<g256, 256, MG_SMEM>>>(px1h, px1l, CC, nullptr, nullptr, 0,
        pWqkh, pWqkl, bqk, nullptr, nullptr, nullptr, nullptr, pq1, CC, qscale, 3);
    mma_gemm<<<g256, 256, MG_SMEM>>>(px0h, px0l, CC, nullptr, nullptr, 0,
        pWvh, pWvl, bv, nullptr, nullptr, nullptr, nullptr, pv0, CC, 1.f, 3);
    mma_gemm<<<g256, 256, MG_SMEM>>>(px1h, px1l, CC, nullptr, nullptr, 0,
        pWvh, pWvl, bv, nullptr, nullptr, nullptr, nullptr, pv1, CC, 1.f, 3);

    dim3 fg(LL / 128, BB * HH, 2);
    flash_mma<<<fg, 256, FK_SMEM>>>(pq0, pq1, pv0, pv1,
                                    pm0h, pm0l, pm1h, pm1l);

    mma_gemm<<<g256, 256, MG_SMEM>>>(pm0h, pm0l, CC, nullptr, nullptr, 0,
        pWoth, pWotl, bout, nullptr, nullptr, pp0h, pp0l, nullptr, CC, 1.f, 2);
    mma_gemm<<<g256, 256, MG_SMEM>>>(pm1h, pm1l, CC, nullptr, nullptr, 0,
        pWoth, pWotl, bout, nullptr, nullptr, pp1h, pp1l, nullptr, CC, 1.f, 2);

    mma_gemm<<<g512, 256, MG_SMEM>>>(px0h, px0l, CC, pp0h, pp0l, CC,
        pW1h, pW1l, b1, nullptr, p_h0, nullptr, nullptr, nullptr, C2, 1.f, 0);
    mma_gemm<<<g512, 256, MG_SMEM>>>(px1h, px1l, CC, pp1h, pp1l, CC,
        pW1h, pW1l, b1, nullptr, p_h1, nullptr, nullptr, nullptr, C2, 1.f, 0);

    dim3 lg(RR, 2);
    ln_gelu_kernel<<<lg, 256>>>(p_h0, p_h1, ph0h, ph0l, ph1h, ph1l, ln_g, ln_b);

    mma_gemm<<<g256, 256, MG_SMEM>>>(ph0h, ph0l, C2, nullptr, nullptr, 0,
        pW2h, pW2l, b2, x0, out, nullptr, nullptr, nullptr, CC, 1.f, 0);
    mma_gemm<<<g256, 256, MG_SMEM>>>(ph1h, ph1l, C2, nullptr, nullptr, 0,
        pW2h, pW2l, b2, x1, out + (size_t)RR * CC, nullptr, nullptr, nullptr, CC, 1.f, 0);
}

// round 11
// speedup vs baseline: 4.5768x; 1.6618x over previous
#include <cuda_runtime.h>
#include <cuda_fp16.h>
#include <math.h>
#include <stdint.h>

#define BB 8
#define LL 2048
#define CC 256
#define HH 4
#define DDIM 64
#define RR (BB*LL)
#define C2 (2*CC)
#define SHIFT 4.0f

typedef unsigned int u32;
typedef __half f16;

__device__ __forceinline__ u32 pack_h2(float a, float b) {
    __half2 t = __halves2half2(__float2half_rn(a), __float2half_rn(b));
    return *(u32*)&t;
}
__device__ __forceinline__ u32 smem_u32(const void* p) {
    u32 a;
    asm("{ .reg .u64 t; cvta.to.shared.u64 t, %1; cvt.u32.u64 %0, t; }"
        : "=r"(a) : "l"(p));
    return a;
}
__device__ __forceinline__ void ldsm4(u32 addr, u32& r0, u32& r1, u32& r2, u32& r3) {
    asm volatile("ldmatrix.sync.aligned.m8n8.x4.shared.b16 {%0,%1,%2,%3}, [%4];"
                 : "=r"(r0), "=r"(r1), "=r"(r2), "=r"(r3) : "r"(addr));
}
__device__ __forceinline__ void ldsm4t(u32 addr, u32& r0, u32& r1, u32& r2, u32& r3) {
    asm volatile("ldmatrix.sync.aligned.m8n8.x4.trans.shared.b16 {%0,%1,%2,%3}, [%4];"
                 : "=r"(r0), "=r"(r1), "=r"(r2), "=r"(r3) : "r"(addr));
}
__device__ __forceinline__ void mma_f16(float* c, const u32* a, const u32* b) {
    asm volatile(
        "mma.sync.aligned.m16n8k16.row.col.f32.f16.f16.f32 "
        "{%0,%1,%2,%3},{%4,%5,%6,%7},{%8,%9},{%0,%1,%2,%3};"
        : "+f"(c[0]), "+f"(c[1]), "+f"(c[2]), "+f"(c[3])
        : "r"(a[0]), "r"(a[1]), "r"(a[2]), "r"(a[3]), "r"(b[0]), "r"(b[1]));
}
#define CP_ASYNC16(smem, gptr) \
    asm volatile("cp.async.cg.shared.global [%0], [%1], 16;" \
                 :: "r"(smem), "l"(gptr) : "memory")
#define CP_COMMIT() asm volatile("cp.async.commit_group;" ::: "memory")
#define CP_WAIT1()  asm volatile("cp.async.wait_group 1;" ::: "memory")
#define CP_WAIT0()  asm volatile("cp.async.wait_group 0;" ::: "memory")

// ===================== scratch =====================
__device__ float g_h0 [RR*C2];
__device__ float g_h1 [RR*C2];

__device__ f16 g_x0f[RR*CC], g_x1f[RR*CC];
__device__ f16 g_m0 [RR*CC], g_m1 [RR*CC];
__device__ f16 g_p0 [RR*CC], g_p1 [RR*CC];
__device__ f16 g_h0f[RR*C2], g_h1f[RR*C2];

__device__ f16 g_qk0[BB*HH*LL*DDIM];
__device__ f16 g_qk1[BB*HH*LL*DDIM];
__device__ f16 g_v0 [BB*HH*LL*DDIM];
__device__ f16 g_v1 [BB*HH*LL*DDIM];

__device__ f16 g_Wqk[CC*CC];
__device__ f16 g_Wv [CC*CC];
__device__ f16 g_Wot[CC*CC];
__device__ f16 g_W1 [C2*C2];
__device__ f16 g_W2 [CC*C2];   // [N=256][K=512]

// ===================== f32 -> f16 =====================
__global__ __launch_bounds__(256) void tof16_kernel(
    const float* __restrict__ x, f16* __restrict__ y, int n)
{
    int i = (blockIdx.x * 256 + threadIdx.x) * 4;
    if (i >= n) return;
    float4 v = *(const float4*)(x + i);
    uint2 u;
    u.x = pack_h2(v.x, v.y);
    u.y = pack_h2(v.z, v.w);
    *(uint2*)(y + i) = u;
}

// ===================== transpose W [K,N] -> f16 [N,K] =====================
__global__ __launch_bounds__(256) void wt_kernel(
    const float* __restrict__ W, f16* __restrict__ o, int K, int N)
{
    __shared__ float t[32][33];
    int nb = blockIdx.x * 32, kb = blockIdx.y * 32;
    int tx = threadIdx.x, ty0 = threadIdx.y;
    #pragma unroll
    for (int r = 0; r < 4; r++) {
        int ty = ty0 + r * 8;
        t[ty][tx] = W[(size_t)(kb + ty) * N + nb + tx];
    }
    __syncthreads();
    #pragma unroll
    for (int r = 0; r < 4; r++) {
        int ty = ty0 + r * 8;
        o[(size_t)(nb + ty) * K + kb + tx] = __float2half_rn(t[tx][ty]);
    }
}

// ===================== single-pass fp16 mma GEMM, cp.async 2-stage =====================
// out[M,N] = (concat(A0,A1)[M,K] @ W^T[N,K] + bias)*scale (+res)
// mode: 0 = f32 out (+res), 3 = f16 head-layout, 4 = f16 plain
#define MG_SMEM (64*1024 + 128)

__global__ __launch_bounds__(256, 2) void mma_gemm(
    const f16* __restrict__ a0, int K0,
    const f16* __restrict__ a1, int K1,
    const f16* __restrict__ bw,
    const float* __restrict__ bias,
    const float* __restrict__ res,
    float* __restrict__ outf,
    f16* __restrict__ outh,
    int N, float scale, int mode)
{
    extern __shared__ char dsm[];
    u32 sb0 = smem_u32(dsm);
    u32 sb  = (sb0 + 127) & ~127u;
    char* smp = dsm + (sb - sb0);

    const int tid  = threadIdx.x;
    const int wid  = tid >> 5;
    const int lane = tid & 31;

    const int m0 = blockIdx.y * 128;
    const int n0 = blockIdx.x * 128;
    const int KB = K0 + K1;
    const int nc0 = K0 >> 6;
    const int nc  = KB >> 6;

    const int wm = (wid >> 2) * 64;
    const int wn = (wid & 3) * 32;

    const int ld_row = tid >> 3;     // with 4 reps -> 128 rows, 8 chunks
    const int ld_ch  = tid & 7;

    float acc[4][4][4];
    #pragma unroll
    for (int i = 0; i < 4; i++)
        #pragma unroll
        for (int j = 0; j < 4; j++)
            #pragma unroll
            for (int t = 0; t < 4; t++) acc[i][j][t] = 0.f;

    // prefetch chunk 0 (stage 0): A 16KB + B 16KB
    {
        char* tb = smp;
        #pragma unroll
        for (int i = 0; i < 4; i++) {
            int row = ld_row + i * 32;
            u32 off = (u32)(row * 128 + ((ld_ch ^ (row & 7)) << 4));
            const f16* Ap = (0 < nc0) ? a0 : a1;
            int astr = (0 < nc0) ? K0 : K1;
            CP_ASYNC16(sb + off,
                       (const char*)(Ap + (size_t)(m0 + row) * astr + ld_ch * 8));
            CP_ASYNC16(sb + 16384 + off,
                       (const char*)(bw + (size_t)(n0 + row) * KB + ld_ch * 8));
        }
        (void)tb;
        CP_COMMIT();
    }

    for (int c = 0; c < nc; c++) {
        const u32 bufA = sb + (u32)(c & 1) * 32768;
        const u32 bufB = bufA + 16384;

        if (c + 1 < nc) {
            u32 stgA = sb + (u32)((c + 1) & 1) * 32768;
            const f16* Ap; int astr, koff;
            if (c + 1 < nc0) { Ap = a0; astr = K0; koff = (c + 1) << 6; }
            else             { Ap = a1; astr = K1; koff = (c + 1 - nc0) << 6; }
            const int koffB = (c + 1) << 6;
            #pragma unroll
            for (int i = 0; i < 4; i++) {
                int row = ld_row + i * 32;
                u32 off = (u32)(row * 128 + ((ld_ch ^ (row & 7)) << 4));
                CP_ASYNC16(stgA + off,
                           (const char*)(Ap + (size_t)(m0 + row) * astr + koff + ld_ch * 8));
                CP_ASYNC16(stgA + 16384 + off,
                           (const char*)(bw + (size_t)(n0 + row) * KB + koffB + ld_ch * 8));
            }
            CP_COMMIT();
            CP_WAIT1();
        } else {
            CP_WAIT0();
        }
        __syncthreads();

        #pragma unroll
        for (int ks = 0; ks < 4; ks++) {
            const int cidx = ks * 2 + (lane >> 4);
            u32 bf[4][2];
            #pragma unroll
            for (int g = 0; g < 2; g++) {
                int rb = wn + g * 16 + (lane & 15);
                u32 off = (u32)(rb * 128 + ((cidx ^ (rb & 7)) << 4));
                u32 r0, r1, r2, r3;
                ldsm4(bufB + off, r0, r1, r2, r3);
                bf[2*g][0] = r0; bf[2*g][1] = r2;
                bf[2*g+1][0] = r1; bf[2*g+1][1] = r3;
            }
            u32 af[4][4];
            #pragma unroll
            for (int mi = 0; mi < 4; mi++) {
                int ra = wm + mi * 16 + (lane & 15);
                u32 off = (u32)(ra * 128 + ((cidx ^ (ra & 7)) << 4));
                ldsm4(bufA + off, af[mi][0], af[mi][1], af[mi][2], af[mi][3]);
            }
            #pragma unroll
            for (int mi = 0; mi < 4; mi++)
                #pragma unroll
                for (int nj = 0; nj < 4; nj++)
                    mma_f16(acc[mi][nj], af[mi], bf[nj]);
        }
        __syncthreads();
    }

    const int lr = lane >> 2;
    const int lc = (lane & 3) * 2;
    #pragma unroll
    for (int mi = 0; mi < 4; mi++) {
        #pragma unroll
        for (int half = 0; half < 2; half++) {
            int r = m0 + wm + mi * 16 + lr + half * 8;
            #pragma unroll
            for (int nj = 0; nj < 4; nj++) {
                int col = n0 + wn + nj * 8 + lc;
                float2 bv = *(const float2*)(bias + col);
                float v0 = (acc[mi][nj][half * 2]     + bv.x) * scale;
                float v1 = (acc[mi][nj][half * 2 + 1] + bv.y) * scale;
                if (mode == 0) {
                    size_t o = (size_t)r * N + col;
                    if (res) {
                        float2 rv = *(const float2*)(res + o);
                        v0 += rv.x; v1 += rv.y;
                    }
                    *(float2*)(outf + o) = make_float2(v0, v1);
                } else if (mode == 4) {
                    size_t o = (size_t)r * N + col;
                    *(u32*)(outh + o) = pack_h2(v0, v1);
                } else { // mode 3: head-layout f16
                    int b_ = r >> 11, l = r & 2047;
                    int h  = col >> 6, d = col & 63;
                    size_t o = (((size_t)(b_ * HH + h)) * LL + l) * DDIM + d;
                    *(u32*)(outh + o) = pack_h2(v0, v1);
                }
            }
        }
    }
}

// ===================== flash attention (fp16, fixed shift, BK=32 sub-tiles) =====================
#define FK_SMEM (48*1024 + 128)

__global__ __launch_bounds__(256, 2) void flash_mma(
    const f16* __restrict__ qk0, const f16* __restrict__ qk1,
    const f16* __restrict__ v0,  const f16* __restrict__ v1,
    f16* __restrict__ m0, f16* __restrict__ m1)
{
    extern __shared__ char dsm[];
    u32 sb0 = smem_u32(dsm);
    u32 sb  = (sb0 + 127) & ~127u;
    char* smp = dsm + (sb - sb0);

    const int dir = blockIdx.z;
    const f16* qh = dir ? qk1 : qk0;
    const f16* kh = dir ? qk0 : qk1;
    const f16* vh = dir ? v0 : v1;
    f16* mo = dir ? m1 : m0;

    const int bh = blockIdx.y;
    const size_t base = (size_t)bh * LL * DDIM;
    const int q0 = blockIdx.x * 128;
    const int tid  = threadIdx.x;
    const int wid  = tid >> 5;
    const int lane = tid & 31;
    const int g  = lane >> 2;
    const int t4 = lane & 3;
    const int rb = lane & 15;
    const int chsel = lane >> 4;

    const u32 sQ  = sb;
    const u32 sStage = sb + 16384;

    #pragma unroll
    for (int rep = 0; rep < 2; rep++) {
        int idx = rep * 256 + tid;
        int row = idx >> 2, ch2 = idx & 3;
        #pragma unroll
        for (int s = 0; s < 2; s++) {
            int ch = ch2 * 2 + s;
            u32 soff = (u32)(row * 128 + ((ch ^ (row & 7)) << 4));
            *(uint4*)(smp + soff) =
                *(const uint4*)(qh + base + (size_t)(q0 + row) * DDIM + ch * 8);
        }
    }

    const int pf_row = tid >> 2;
    const int pf_ch2 = tid & 3;

    {
        u32 stg = sStage;
        #pragma unroll
        for (int s = 0; s < 2; s++) {
            int ch = pf_ch2 * 2 + s;
            u32 soff = (u32)(pf_row * 128 + ((ch ^ (pf_row & 7)) << 4));
            size_t goff = base + (size_t)pf_row * DDIM + ch * 8;
            CP_ASYNC16(stg + soff, (const char*)(kh + goff));
            CP_ASYNC16(stg + 8192 + soff, (const char*)(vh + goff));
        }
        CP_COMMIT();
    }
    __syncthreads();

    u32 qf[4][4];
    {
        int qr = wid * 16 + rb;
        #pragma unroll
        for (int ks = 0; ks < 4; ks++) {
            int chunk = ks * 2 + chsel;
            u32 off = (u32)(qr * 128 + ((chunk ^ (qr & 7)) << 4));
            ldsm4(sQ + off, qf[ks][0], qf[ks][1], qf[ks][2], qf[ks][3]);
        }
    }

    float lrow0 = 0.f, lrow1 = 0.f;
    float oacc[8][4];
    #pragma unroll
    for (int dt = 0; dt < 8; dt++)
        #pragma unroll
        for (int t = 0; t < 4; t++) oacc[dt][t] = 0.f;

    for (int it = 0; it < 32; it++) {
        const u32 bufK = sStage + (u32)(it & 1) * 16384;
        const u32 bufV = bufK + 8192;

        if (it + 1 < 32) {
            u32 stg = sStage + (u32)((it + 1) & 1) * 16384;
            int k0n = (it + 1) * 64;
            #pragma unroll
            for (int s = 0; s < 2; s++) {
                int ch = pf_ch2 * 2 + s;
                u32 soff = (u32)(pf_row * 128 + ((ch ^ (pf_row & 7)) << 4));
                size_t goff = base + (size_t)(k0n + pf_row) * DDIM + ch * 8;
                CP_ASYNC16(stg + soff, (const char*)(kh + goff));
                CP_ASYNC16(stg + 8192 + soff, (const char*)(vh + goff));
            }
            CP_COMMIT();
            CP_WAIT1();
        } else {
            CP_WAIT0();
        }
        __syncthreads();

        // two sub-tiles of 32 k-cols each (register peak halved)
        #pragma unroll
        for (int half = 0; half < 2; half++) {
            float acc[4][4];
            #pragma unroll
            for (int nt = 0; nt < 4; nt++)
                #pragma unroll
                for (int t = 0; t < 4; t++) acc[nt][t] = 0.f;

            // S = Qh Kh^T (32 cols)
            #pragma unroll
            for (int ks = 0; ks < 4; ks++) {
                int chunk = ks * 2 + chsel;
                #pragma unroll
                for (int gg = 0; gg < 2; gg++) {
                    int rr = half * 32 + gg * 16 + rb;
                    u32 off = (u32)(rr * 128 + ((chunk ^ (rr & 7)) << 4));
                    u32 r0, r1, r2, r3;
                    ldsm4(bufK + off, r0, r1, r2, r3);
                    { u32 bfa[2] = {r0, r2}; mma_f16(acc[2*gg],   qf[ks], bfa); }
                    { u32 bfb[2] = {r1, r3}; mma_f16(acc[2*gg+1], qf[ks], bfb); }
                }
            }

            // P = exp(S - SHIFT); accumulate row sums
            u32 ph[2][4];
            #pragma unroll
            for (int nt = 0; nt < 4; nt++) {
                acc[nt][0] = __expf(acc[nt][0] - SHIFT);
                acc[nt][1] = __expf(acc[nt][1] - SHIFT);
                acc[nt][2] = __expf(acc[nt][2] - SHIFT);
                acc[nt][3] = __expf(acc[nt][3] - SHIFT);
                lrow0 += acc[nt][0] + acc[nt][1];
                lrow1 += acc[nt][2] + acc[nt][3];
            }
            #pragma unroll
            for (int kb = 0; kb < 2; kb++) {
                ph[kb][0] = pack_h2(acc[2*kb][0],   acc[2*kb][1]);
                ph[kb][1] = pack_h2(acc[2*kb][2],   acc[2*kb][3]);
                ph[kb][2] = pack_h2(acc[2*kb+1][0], acc[2*kb+1][1]);
                ph[kb][3] = pack_h2(acc[2*kb+1][2], acc[2*kb+1][3]);
            }

            // O += P V  (V rows half*32 .. half*32+31)
            #pragma unroll
            for (int kb = 0; kb < 2; kb++) {
                int rr = half * 32 + kb * 16 + rb;
                #pragma unroll
                for (int dg = 0; dg < 4; dg++) {
                    int chunk = dg * 2 + chsel;
                    u32 off = (u32)(rr * 128 + ((chunk ^ (rr & 7)) << 4));
                    u32 r0, r1, r2, r3;
                    ldsm4t(bufV + off, r0, r1, r2, r3);
                    { u32 vfa[2] = {r0, r1}; mma_f16(oacc[2*dg],   ph[kb], vfa); }
                    { u32 vfb[2] = {r2, r3}; mma_f16(oacc[2*dg+1], ph[kb], vfb); }
                }
            }
        }
        __syncthreads();
    }

    lrow0 += __shfl_xor_sync(0xffffffffu, lrow0, 1);
    lrow0 += __shfl_xor_sync(0xffffffffu, lrow0, 2);
    lrow1 += __shfl_xor_sync(0xffffffffu, lrow1, 1);
    lrow1 += __shfl_xor_sync(0xffffffffu, lrow1, 2);

    float inv0 = 1.f / lrow0, inv1 = 1.f / lrow1;
    int r0g = q0 + wid * 16 + g;
    int bb = bh >> 2, hh = bh & 3;
    #pragma unroll
    for (int dt = 0; dt < 8; dt++) {
        int col = hh * DDIM + dt * 8 + t4 * 2;
        size_t o0 = (size_t)(bb * LL + r0g) * CC + col;
        size_t o1 = (size_t)(bb * LL + r0g + 8) * CC + col;
        *(u32*)(mo + o0) = pack_h2(oacc[dt][0] * inv0, oacc[dt][1] * inv0);
        *(u32*)(mo + o1) = pack_h2(oacc[dt][2] * inv1, oacc[dt][3] * inv1);
    }
}

// ===================== LayerNorm + exact GELU -> f16 =====================
__global__ __launch_bounds__(256) void ln_gelu_kernel(
    const float* __restrict__ h0, const float* __restrict__ h1,
    f16* __restrict__ h0f, f16* __restrict__ h1f,
    const float* __restrict__ g, const float* __restrict__ bta)
{
    const float* hp = blockIdx.y ? h1 : h0;
    f16* oh = blockIdx.y ? h1f : h0f;
    const size_t rowoff = (size_t)blockIdx.x * C2;
    const int tid = threadIdx.x;
    const int lane = tid & 31, wid = tid >> 5;

    float2 v = *(const float2*)&hp[rowoff + tid * 2];
    float s  = v.x + v.y;
    float sq = v.x * v.x + v.y * v.y;
    #pragma unroll
    for (int off = 16; off; off >>= 1) {
        s  += __shfl_xor_sync(0xffffffffu, s,  off);
        sq += __shfl_xor_sync(0xffffffffu, sq, off);
    }
    __shared__ float rs[8], rq[8];
    if (lane == 0) { rs[wid] = s; rq[wid] = sq; }
    __syncthreads();
    if (wid == 0) {
        s  = (lane < 8) ? rs[lane] : 0.f;
        sq = (lane < 8) ? rq[lane] : 0.f;
        #pragma unroll
        for (int off = 4; off; off >>= 1) {
            s  += __shfl_xor_sync(0xffffffffu, s,  off);
            sq += __shfl_xor_sync(0xffffffffu, sq, off);
        }
        if (lane == 0) { rs[0] = s; rq[0] = sq; }
    }
    __syncthreads();
    float mean = rs[0] * (1.f / 512.f);
    float var  = rq[0] * (1.f / 512.f) - mean * mean;
    float rstd = rsqrtf(var + 1e-5f);

    int c0 = tid * 2;
    float x0n = (v.x - mean) * rstd * g[c0]     + bta[c0];
    float x1n = (v.y - mean) * rstd * g[c0 + 1] + bta[c0 + 1];
    x0n = 0.5f * x0n * (1.f + erff(x0n * 0.70710678118654752f));
    x1n = 0.5f * x1n * (1.f + erff(x1n * 0.70710678118654752f));

    *(u32*)(oh + rowoff + c0) = pack_h2(x0n, x1n);
}

// ===================== launch =====================
extern "C" void kernel_launch(void* const* d_in, const int* in_sizes, int n_in,
                              void* d_out, int out_size)
{
    const float* x0   = (const float*)d_in[0];
    const float* x1   = (const float*)d_in[1];
    const float* Wqk  = (const float*)d_in[2];
    const float* bqk  = (const float*)d_in[3];
    const float* Wv   = (const float*)d_in[4];
    const float* bv   = (const float*)d_in[5];
    const float* Wout = (const float*)d_in[6];
    const float* bout = (const float*)d_in[7];
    const float* W1   = (const float*)d_in[8];
    const float* b1   = (const float*)d_in[9];
    const float* ln_g = (const float*)d_in[10];
    const float* ln_b = (const float*)d_in[11];
    const float* W2   = (const float*)d_in[12];
    const float* b2   = (const float*)d_in[13];
    float* out = (float*)d_out;

    float *p_h0, *p_h1;
    f16 *px0f, *px1f, *pm0, *pm1, *pp0, *pp1, *ph0f, *ph1f;
    f16 *pq0, *pq1, *pv0, *pv1;
    f16 *pWqk, *pWv, *pWot, *pW1, *pW2;

    cudaGetSymbolAddress((void**)&p_h0,  g_h0);
    cudaGetSymbolAddress((void**)&p_h1,  g_h1);
    cudaGetSymbolAddress((void**)&px0f, g_x0f); cudaGetSymbolAddress((void**)&px1f, g_x1f);
    cudaGetSymbolAddress((void**)&pm0,  g_m0);  cudaGetSymbolAddress((void**)&pm1,  g_m1);
    cudaGetSymbolAddress((void**)&pp0,  g_p0);  cudaGetSymbolAddress((void**)&pp1,  g_p1);
    cudaGetSymbolAddress((void**)&ph0f, g_h0f); cudaGetSymbolAddress((void**)&ph1f, g_h1f);
    cudaGetSymbolAddress((void**)&pq0,  g_qk0); cudaGetSymbolAddress((void**)&pq1,  g_qk1);
    cudaGetSymbolAddress((void**)&pv0,  g_v0);  cudaGetSymbolAddress((void**)&pv1,  g_v1);
    cudaGetSymbolAddress((void**)&pWqk, g_Wqk);
    cudaGetSymbolAddress((void**)&pWv,  g_Wv);
    cudaGetSymbolAddress((void**)&pWot, g_Wot);
    cudaGetSymbolAddress((void**)&pW1,  g_W1);
    cudaGetSymbolAddress((void**)&pW2,  g_W2);

    cudaFuncSetAttribute(mma_gemm,
                         cudaFuncAttributeMaxDynamicSharedMemorySize, MG_SMEM);
    cudaFuncSetAttribute(flash_mma,
                         cudaFuncAttributeMaxDynamicSharedMemorySize, FK_SMEM);

    const float qscale = 0.35355339059327373f; // 64^-0.25

    tof16_kernel<<<RR * CC / 1024, 256>>>(x0, px0f, RR * CC);
    tof16_kernel<<<RR * CC / 1024, 256>>>(x1, px1f, RR * CC);
    wt_kernel<<<dim3(CC/32, CC/32), dim3(32,8)>>>(Wqk,  pWqk, CC, CC);
    wt_kernel<<<dim3(CC/32, CC/32), dim3(32,8)>>>(Wv,   pWv,  CC, CC);
    wt_kernel<<<dim3(CC/32, CC/32), dim3(32,8)>>>(Wout, pWot, CC, CC);
    wt_kernel<<<dim3(C2/32, C2/32), dim3(32,8)>>>(W1,   pW1,  C2, C2);
    wt_kernel<<<dim3(CC/32, C2/32), dim3(32,8)>>>(W2,   pW2,  C2, CC);

    dim3 g256(2, 128);
    dim3 g512(4, 128);

    // QK / V projections -> f16 head layout
    mma_gemm<<<g256, 256, MG_SMEM>>>(px0f, CC, nullptr, 0,
        pWqk, bqk, nullptr, nullptr, pq0, CC, qscale, 3);
    mma_gemm<<<g256, 256, MG_SMEM>>>(px1f, CC, nullptr, 0,
        pWqk, bqk, nullptr, nullptr, pq1, CC, qscale, 3);
    mma_gemm<<<g256, 256, MG_SMEM>>>(px0f, CC, nullptr, 0,
        pWv, bv, nullptr, nullptr, pv0, CC, 1.f, 3);
    mma_gemm<<<g256, 256, MG_SMEM>>>(px1f, CC, nullptr, 0,
        pWv, bv, nullptr, nullptr, pv1, CC, 1.f, 3);

    // dual flash attention -> f16 merged
    dim3 fg(LL / 128, BB * HH, 2);
    flash_mma<<<fg, 256, FK_SMEM>>>(pq0, pq1, pv0, pv1, pm0, pm1);

    // output projection -> f16
    mma_gemm<<<g256, 256, MG_SMEM>>>(pm0, CC, nullptr, 0,
        pWot, bout, nullptr, nullptr, pp0, CC, 1.f, 4);
    mma_gemm<<<g256, 256, MG_SMEM>>>(pm1, CC, nullptr, 0,
        pWot, bout, nullptr, nullptr, pp1, CC, 1.f, 4);

    // FFN-1 on virtual concat([x, p]) -> f32
    mma_gemm<<<g512, 256, MG_SMEM>>>(px0f, CC, pp0, CC,
        pW1, b1, nullptr, p_h0, nullptr, C2, 1.f, 0);
    mma_gemm<<<g512, 256, MG_SMEM>>>(px1f, CC, pp1, CC,
        pW1, b1, nullptr, p_h1, nullptr, C2, 1.f, 0);

    // LayerNorm + GELU -> f16
    dim3 lg(RR, 2);
    ln_gelu_kernel<<<lg, 256>>>(p_h0, p_h1, ph0f, ph1f, ln_g, ln_b);

    // FFN-2 + residual -> outputs
    mma_gemm<<<g256, 256, MG_SMEM>>>(ph0f, C2, nullptr, 0,
        pW2, b2, x0, out, nullptr, CC, 1.f, 0);
    mma_gemm<<<g256, 256, MG_SMEM>>>(ph1f, C2, nullptr, 0,
        pW2, b2, x1, out + (size_t)RR * CC, nullptr, CC, 1.f, 0);
}